// round 5
// baseline (speedup 1.0000x reference)
#include <cuda_runtime.h>

#define TT   256
#define HH   30
#define INP  3
#define NB   4            // batch elements per team
#define NTHR 96           // 3 warps = 1 team per block

typedef unsigned long long ull;

// ---- f32x2 packed helpers (sm_103a) ----
__device__ __forceinline__ ull fma2(ull a, ull b, ull c) {
    ull d; asm("fma.rn.f32x2 %0,%1,%2,%3;" : "=l"(d) : "l"(a), "l"(b), "l"(c)); return d;
}
__device__ __forceinline__ ull pk2(float lo, float hi) {
    ull r; asm("mov.b64 %0,{%1,%2};" : "=l"(r) : "f"(lo), "f"(hi)); return r;
}
__device__ __forceinline__ void upk2(ull v, float& lo, float& hi) {
    asm("mov.b64 {%0,%1},%2;" : "=f"(lo), "=f"(hi) : "l"(v));
}

__device__ __forceinline__ float sigf(float x) {
    return __fdividef(1.0f, 1.0f + __expf(-x));
}
__device__ __forceinline__ float tanh_fast(float x) {
    return __fdividef(2.0f, 1.0f + __expf(-2.0f * x)) - 1.0f;
}

__global__ void __launch_bounds__(NTHR)
stacked_lstm_kernel(const float* __restrict__ x,
                    const float* __restrict__ Wih0, const float* __restrict__ Whh0,
                    const float* __restrict__ bih0, const float* __restrict__ bhh0,
                    const float* __restrict__ Wih1, const float* __restrict__ Whh1,
                    const float* __restrict__ bih1, const float* __restrict__ bhh1,
                    const float* __restrict__ Wfc1, const float* __restrict__ bfc1,
                    const float* __restrict__ Wfc2, const float* __restrict__ bfc2,
                    const float* __restrict__ Wfc3, const float* __restrict__ bfc3,
                    float* __restrict__ out, int B)
{
    // Double-buffered h0 (duplicated pairs for f32x2), partial gates, and h1.
    __shared__ float4     h0buf[2][2 * HH];     // [buf][g*HH+k] = (h_{2g},h_{2g},h_{2g+1},h_{2g+1})
    __shared__ ulonglong2 pbuf[2][4][HH];       // [buf][IF01,IF23,GO01,GO23][j]
    __shared__ float4     h1buf[2 * HH];        // single buffer (producer == consumer warp)

    const int tid = threadIdx.x;

    // zero h0buf + h1buf (h(-1) = 0)
    {
        float* z0 = (float*)h0buf;
        for (int i = tid; i < 2 * 2 * HH * 4; i += NTHR) z0[i] = 0.0f;
        float* z1 = (float*)h1buf;
        for (int i = tid; i < 2 * HH * 4; i += NTHR) z1[i] = 0.0f;
    }
    __syncthreads();

    const int  wid  = tid >> 5;                 // 0 = layer0, 1 = Wih1 partial, 2 = Whh1 + act
    const int  lane = tid & 31;
    const int  jj   = lane < HH ? lane : HH - 1;
    const long wb   = (long)blockIdx.x * NB;
    if (wb >= B) return;                        // uniform per block

    // ---- role-selected weight matrix -> registers (120 regs, k fully unrolled) ----
    const float* Wsel = (wid == 0) ? Whh0 : (wid == 1) ? Wih1 : Whh1;
    ull wIF[HH], wGO[HH];
    #pragma unroll
    for (int k = 0; k < HH; k++) {
        wIF[k] = pk2(Wsel[jj * HH + k],        Wsel[(jj + 30) * HH + k]);
        wGO[k] = pk2(Wsel[(jj + 60) * HH + k], Wsel[(jj + 90) * HH + k]);
    }

    // biases: warp0 uses b0, warp1 uses b1 (warp2 gets bias via partial)
    ull bIF, bGO;
    if (wid == 0) {
        bIF = pk2(bih0[jj]      + bhh0[jj],      bih0[jj + 30] + bhh0[jj + 30]);
        bGO = pk2(bih0[jj + 60] + bhh0[jj + 60], bih0[jj + 90] + bhh0[jj + 90]);
    } else {
        bIF = pk2(bih1[jj]      + bhh1[jj],      bih1[jj + 30] + bhh1[jj + 30]);
        bGO = pk2(bih1[jj + 60] + bhh1[jj + 60], bih1[jj + 90] + bhh1[jj + 90]);
    }

    // x weights (only warp0 uses them)
    ull wxIF[INP], wxGO[INP];
    #pragma unroll
    for (int c = 0; c < INP; c++) {
        wxIF[c] = (wid == 0) ? pk2(Wih0[jj * INP + c],        Wih0[(jj + 30) * INP + c]) : 0ull;
        wxGO[c] = (wid == 0) ? pk2(Wih0[(jj + 60) * INP + c], Wih0[(jj + 90) * INP + c]) : 0ull;
    }

    const float* xbase = x + (size_t)wb * TT * INP;
    float cc[NB], h1s[NB];
    #pragma unroll
    for (int e = 0; e < NB; e++) { cc[e] = 0.0f; h1s[e] = 0.0f; }

    // ================= pipelined phase loop =================
    for (int p = 0; p < TT + 2; p++) {
        const int rb = (p + 1) & 1;             // read buffer (previous phase's writes)
        const int wbf = p & 1;                  // write buffer
        const bool active = (wid == 0) ? (p < TT)
                          : (wid == 1) ? (p >= 1 && p < TT + 1)
                                       : (p >= 2);
        if (active) {
            ull aIF[NB], aGO[NB];

            // x loads issued early (warp0), latency hidden behind MAC loop
            float xv[NB][INP];
            if (wid == 0) {
                #pragma unroll
                for (int e = 0; e < NB; e++) {
                    const float* xp = xbase + ((size_t)e * TT + p) * INP;
                    xv[e][0] = xp[0]; xv[e][1] = xp[1]; xv[e][2] = xp[2];
                }
            }

            // accumulator init
            if (wid == 2) {
                ulonglong2 q0 = pbuf[rb][0][jj], q1 = pbuf[rb][1][jj];
                ulonglong2 q2 = pbuf[rb][2][jj], q3 = pbuf[rb][3][jj];
                aIF[0] = q0.x; aIF[1] = q0.y; aIF[2] = q1.x; aIF[3] = q1.y;
                aGO[0] = q2.x; aGO[1] = q2.y; aGO[2] = q3.x; aGO[3] = q3.y;
            } else {
                #pragma unroll
                for (int e = 0; e < NB; e++) { aIF[e] = bIF; aGO[e] = bGO; }
            }

            // MAC over 30 hidden units; h from broadcast smem, weights from regs
            const ulonglong2* hp = (wid == 2) ? (const ulonglong2*)h1buf
                                              : (const ulonglong2*)h0buf[rb];
            #pragma unroll
            for (int k = 0; k < HH; k++) {
                ulonglong2 hA = hp[k], hB = hp[HH + k];
                aIF[0] = fma2(wIF[k], hA.x, aIF[0]); aGO[0] = fma2(wGO[k], hA.x, aGO[0]);
                aIF[1] = fma2(wIF[k], hA.y, aIF[1]); aGO[1] = fma2(wGO[k], hA.y, aGO[1]);
                aIF[2] = fma2(wIF[k], hB.x, aIF[2]); aGO[2] = fma2(wGO[k], hB.x, aGO[2]);
                aIF[3] = fma2(wIF[k], hB.y, aIF[3]); aGO[3] = fma2(wGO[k], hB.y, aGO[3]);
            }

            if (wid == 1) {
                // publish partial layer-1 gates (includes b1)
                if (lane < HH) {
                    pbuf[wbf][0][jj] = make_ulonglong2(aIF[0], aIF[1]);
                    pbuf[wbf][1][jj] = make_ulonglong2(aIF[2], aIF[3]);
                    pbuf[wbf][2][jj] = make_ulonglong2(aGO[0], aGO[1]);
                    pbuf[wbf][3][jj] = make_ulonglong2(aGO[2], aGO[3]);
                }
            } else {
                // fold x contribution (warp0) after MAC so LDG latency is hidden
                if (wid == 0) {
                    #pragma unroll
                    for (int e = 0; e < NB; e++) {
                        ull d0 = pk2(xv[e][0], xv[e][0]);
                        ull d1 = pk2(xv[e][1], xv[e][1]);
                        ull d2 = pk2(xv[e][2], xv[e][2]);
                        aIF[e] = fma2(wxIF[0], d0, fma2(wxIF[1], d1, fma2(wxIF[2], d2, aIF[e])));
                        aGO[e] = fma2(wxGO[0], d0, fma2(wxGO[1], d1, fma2(wxGO[2], d2, aGO[e])));
                    }
                }
                // activations
                float hn[NB];
                #pragma unroll
                for (int e = 0; e < NB; e++) {
                    float ui, uf, ug, uo;
                    upk2(aIF[e], ui, uf); upk2(aGO[e], ug, uo);
                    float ig = sigf(ui), fg = sigf(uf), gg = tanh_fast(ug), og = sigf(uo);
                    float c = fmaf(fg, cc[e], ig * gg);
                    cc[e] = c;
                    hn[e] = og * tanh_fast(c);
                }
                if (wid == 0) {
                    float4* wp = h0buf[wbf];
                    if (lane < HH) {
                        wp[jj]      = make_float4(hn[0], hn[0], hn[1], hn[1]);
                        wp[HH + jj] = make_float4(hn[2], hn[2], hn[3], hn[3]);
                    }
                } else { // wid == 2
                    #pragma unroll
                    for (int e = 0; e < NB; e++) h1s[e] = hn[e];
                    __syncwarp();   // all lanes done reading h1buf before overwrite
                    float4* wp = h1buf;
                    if (lane < HH) {
                        wp[jj]      = make_float4(hn[0], hn[0], hn[1], hn[1]);
                        wp[HH + jj] = make_float4(hn[2], hn[2], hn[3], hn[3]);
                    }
                }
            }
        }
        __syncthreads();
    }

    // ================= FC head (warp 2 only) =================
    if (wid == 2) {
        const unsigned FULL = 0xffffffffu;
        float za[NB], zb[NB];
        #pragma unroll
        for (int e = 0; e < NB; e++) { za[e] = bfc1[lane]; zb[e] = bfc1[lane + 32]; }
        for (int k = 0; k < HH; k++) {
            float wa  = Wfc1[lane * HH + k];
            float wbv = Wfc1[(lane + 32) * HH + k];
            #pragma unroll
            for (int e = 0; e < NB; e++) {
                float hk = __shfl_sync(FULL, h1s[e], k);
                za[e] = fmaf(wa, hk, za[e]);
                zb[e] = fmaf(wbv, hk, zb[e]);
            }
        }
        #pragma unroll
        for (int e = 0; e < NB; e++) { za[e] = fmaxf(za[e], 0.f); zb[e] = fmaxf(zb[e], 0.f); }

        float z2[NB];
        #pragma unroll
        for (int e = 0; e < NB; e++) z2[e] = bfc2[lane];
        for (int k = 0; k < 32; k++) {
            float w1 = Wfc2[lane * 64 + k];
            float w2 = Wfc2[lane * 64 + 32 + k];
            #pragma unroll
            for (int e = 0; e < NB; e++) {
                float zak = __shfl_sync(FULL, za[e], k);
                float zbk = __shfl_sync(FULL, zb[e], k);
                z2[e] = fmaf(w1, zak, fmaf(w2, zbk, z2[e]));
            }
        }
        float w3 = Wfc3[lane];
        float b3 = bfc3[0];
        #pragma unroll
        for (int e = 0; e < NB; e++) {
            float pr = w3 * fmaxf(z2[e], 0.f);
            #pragma unroll
            for (int off = 16; off; off >>= 1) pr += __shfl_xor_sync(FULL, pr, off);
            if (lane == 0) out[wb + e] = sigf(pr + b3);
        }
    }
}

extern "C" void kernel_launch(void* const* d_in, const int* in_sizes, int n_in,
                              void* d_out, int out_size)
{
    const float* x    = (const float*)d_in[0];
    const float* Wih0 = (const float*)d_in[1];
    const float* Whh0 = (const float*)d_in[2];
    const float* bih0 = (const float*)d_in[3];
    const float* bhh0 = (const float*)d_in[4];
    const float* Wih1 = (const float*)d_in[5];
    const float* Whh1 = (const float*)d_in[6];
    const float* bih1 = (const float*)d_in[7];
    const float* bhh1 = (const float*)d_in[8];
    const float* Wfc1 = (const float*)d_in[9];
    const float* bfc1 = (const float*)d_in[10];
    const float* Wfc2 = (const float*)d_in[11];
    const float* bfc2 = (const float*)d_in[12];
    const float* Wfc3 = (const float*)d_in[13];
    const float* bfc3 = (const float*)d_in[14];
    float* out = (float*)d_out;

    int B = in_sizes[0] / (TT * INP);          // 8192
    int blocks = (B + NB - 1) / NB;            // 2048 teams

    stacked_lstm_kernel<<<blocks, NTHR>>>(x,
        Wih0, Whh0, bih0, bhh0,
        Wih1, Whh1, bih1, bhh1,
        Wfc1, bfc1, Wfc2, bfc2, Wfc3, bfc3,
        out, B);
}

// round 6
// speedup vs baseline: 1.1076x; 1.1076x over previous
#include <cuda_runtime.h>

#define TT   256
#define HH   30
#define INP  3
#define NB   8            // batch elements per 3-warp team
#define NTHR 96

typedef unsigned long long ull;

__device__ __forceinline__ ull fma2(ull a, ull b, ull c) {
    ull d; asm("fma.rn.f32x2 %0,%1,%2,%3;" : "=l"(d) : "l"(a), "l"(b), "l"(c)); return d;
}
__device__ __forceinline__ ull pk2(float lo, float hi) {
    ull r; asm("mov.b64 %0,{%1,%2};" : "=l"(r) : "f"(lo), "f"(hi)); return r;
}
__device__ __forceinline__ void upk2(ull v, float& lo, float& hi) {
    asm("mov.b64 {%0,%1},%2;" : "=f"(lo), "=f"(hi) : "l"(v));
}
__device__ __forceinline__ float sigf(float x) {
    return __fdividef(1.0f, 1.0f + __expf(-x));
}
__device__ __forceinline__ float tanh_fast(float x) {
    return __fdividef(2.0f, 1.0f + __expf(-2.0f * x)) - 1.0f;
}

__global__ void __launch_bounds__(NTHR, 3)
stacked_lstm_kernel(const float* __restrict__ x,
                    const float* __restrict__ Wih0, const float* __restrict__ Whh0,
                    const float* __restrict__ bih0, const float* __restrict__ bhh0,
                    const float* __restrict__ Wih1, const float* __restrict__ Whh1,
                    const float* __restrict__ bih1, const float* __restrict__ bhh1,
                    const float* __restrict__ Wfc1, const float* __restrict__ bfc1,
                    const float* __restrict__ Wfc2, const float* __restrict__ bfc2,
                    const float* __restrict__ Wfc3, const float* __restrict__ bfc3,
                    float* __restrict__ out, int B)
{
    // h0: double-buffered, 4 element-pair groups of duplicated pairs (f32x2-ready)
    __shared__ float4     h0buf[2][4 * HH];   // [buf][g*HH + k] = (h_{2g},h_{2g},h_{2g+1},h_{2g+1})
    __shared__ float4     h1buf[2][2 * HH];   // [warp-half][g*HH + k] (private to w1 / w2)
    __shared__ ulonglong2 sWh1[HH * HH];      // [k*HH + j] = {IF pair, GO pair} of Whh1

    const int tid  = threadIdx.x;
    const int wid  = tid >> 5;
    const int lane = tid & 31;
    const int jj   = lane < HH ? lane : HH - 1;

    // ---- one-time fills ----
    for (int idx = tid; idx < HH * HH; idx += NTHR) {
        int k = idx / HH, j = idx % HH;
        sWh1[k * HH + j] = make_ulonglong2(
            pk2(Whh1[j * HH + k],        Whh1[(j + 30) * HH + k]),
            pk2(Whh1[(j + 60) * HH + k], Whh1[(j + 90) * HH + k]));
    }
    {
        float* z0 = (float*)h0buf;
        for (int i = tid; i < 2 * 4 * HH * 4; i += NTHR) z0[i] = 0.0f;
        float* z1 = (float*)h1buf;
        for (int i = tid; i < 2 * 2 * HH * 4; i += NTHR) z1[i] = 0.0f;
    }
    __syncthreads();

    const long wb = (long)blockIdx.x * NB;
    if (wb >= B) return;   // uniform per block

    // ---- role-resident weights ----
    const float* Wsel = (wid == 0) ? Whh0 : Wih1;
    ull wIF[HH], wGO[HH];
    #pragma unroll
    for (int k = 0; k < HH; k++) {
        wIF[k] = pk2(Wsel[jj * HH + k],        Wsel[(jj + 30) * HH + k]);
        wGO[k] = pk2(Wsel[(jj + 60) * HH + k], Wsel[(jj + 90) * HH + k]);
    }
    ull bIF, bGO;
    if (wid == 0) {
        bIF = pk2(bih0[jj]      + bhh0[jj],      bih0[jj + 30] + bhh0[jj + 30]);
        bGO = pk2(bih0[jj + 60] + bhh0[jj + 60], bih0[jj + 90] + bhh0[jj + 90]);
    } else {
        bIF = pk2(bih1[jj]      + bhh1[jj],      bih1[jj + 30] + bhh1[jj + 30]);
        bGO = pk2(bih1[jj + 60] + bhh1[jj + 60], bih1[jj + 90] + bhh1[jj + 90]);
    }
    ull wxIF[INP], wxGO[INP];
    #pragma unroll
    for (int c = 0; c < INP; c++) {
        wxIF[c] = (wid == 0) ? pk2(Wih0[jj * INP + c],        Wih0[(jj + 30) * INP + c]) : 0ull;
        wxGO[c] = (wid == 0) ? pk2(Wih0[(jj + 60) * INP + c], Wih0[(jj + 90) * INP + c]) : 0ull;
    }

    const float* xbase = x + (size_t)wb * TT * INP;

    // per-role state
    float c0v[NB];                       // w0 only
    float c1v[4], h1s[4];                // w1/w2 only
    #pragma unroll
    for (int e = 0; e < NB; e++) c0v[e] = 0.0f;
    #pragma unroll
    for (int e = 0; e < 4; e++) { c1v[e] = 0.0f; h1s[e] = 0.0f; }

    const int half = (wid > 0) ? (wid - 1) : 0;

    // ================= phase loop: p = 0..TT =================
    for (int p = 0; p <= TT; p++) {
        if (wid == 0) {
            if (p < TT) {
                // -------- layer 0, t = p, 8 elements --------
                ull aIF[NB], aGO[NB];
                // x term first (short live range)
                #pragma unroll
                for (int e = 0; e < NB; e++) {
                    const float* xp = xbase + ((size_t)e * TT + p) * INP;
                    float x0 = xp[0], x1 = xp[1], x2 = xp[2];
                    ull d0 = pk2(x0, x0), d1 = pk2(x1, x1), d2 = pk2(x2, x2);
                    aIF[e] = fma2(wxIF[0], d0, fma2(wxIF[1], d1, fma2(wxIF[2], d2, bIF)));
                    aGO[e] = fma2(wxGO[0], d0, fma2(wxGO[1], d1, fma2(wxGO[2], d2, bGO)));
                }
                const ulonglong2* hp = (const ulonglong2*)h0buf[(p + 1) & 1];
                #pragma unroll
                for (int k = 0; k < HH; k++) {
                    ulonglong2 hA = hp[k], hB = hp[HH + k], hC = hp[2*HH + k], hD = hp[3*HH + k];
                    aIF[0] = fma2(wIF[k], hA.x, aIF[0]); aGO[0] = fma2(wGO[k], hA.x, aGO[0]);
                    aIF[1] = fma2(wIF[k], hA.y, aIF[1]); aGO[1] = fma2(wGO[k], hA.y, aGO[1]);
                    aIF[2] = fma2(wIF[k], hB.x, aIF[2]); aGO[2] = fma2(wGO[k], hB.x, aGO[2]);
                    aIF[3] = fma2(wIF[k], hB.y, aIF[3]); aGO[3] = fma2(wGO[k], hB.y, aGO[3]);
                    aIF[4] = fma2(wIF[k], hC.x, aIF[4]); aGO[4] = fma2(wGO[k], hC.x, aGO[4]);
                    aIF[5] = fma2(wIF[k], hC.y, aIF[5]); aGO[5] = fma2(wGO[k], hC.y, aGO[5]);
                    aIF[6] = fma2(wIF[k], hD.x, aIF[6]); aGO[6] = fma2(wGO[k], hD.x, aGO[6]);
                    aIF[7] = fma2(wIF[k], hD.y, aIF[7]); aGO[7] = fma2(wGO[k], hD.y, aGO[7]);
                }
                float hn[NB];
                #pragma unroll
                for (int e = 0; e < NB; e++) {
                    float ui, uf, ug, uo;
                    upk2(aIF[e], ui, uf); upk2(aGO[e], ug, uo);
                    float ig = sigf(ui), fg = sigf(uf), gg = tanh_fast(ug), og = sigf(uo);
                    float c = fmaf(fg, c0v[e], ig * gg);
                    c0v[e] = c;
                    hn[e] = og * tanh_fast(c);
                }
                float4* wp = h0buf[p & 1];
                if (lane < HH) {
                    wp[jj]          = make_float4(hn[0], hn[0], hn[1], hn[1]);
                    wp[HH + jj]     = make_float4(hn[2], hn[2], hn[3], hn[3]);
                    wp[2*HH + jj]   = make_float4(hn[4], hn[4], hn[5], hn[5]);
                    wp[3*HH + jj]   = make_float4(hn[6], hn[6], hn[7], hn[7]);
                }
            }
        } else {
            if (p >= 1) {
                // -------- layer 1, t = p-1, 4 elements (eo = half*4) --------
                ull aIF[4], aGO[4];
                #pragma unroll
                for (int e = 0; e < 4; e++) { aIF[e] = bIF; aGO[e] = bGO; }
                const ulonglong2* hp0 = (const ulonglong2*)&h0buf[(p - 1) & 1][half * 2 * HH];
                const ulonglong2* hp1 = (const ulonglong2*)h1buf[half];
                #pragma unroll
                for (int k = 0; k < HH; k++) {
                    ulonglong2 ws = sWh1[k * HH + jj];
                    ulonglong2 hA = hp0[k], hB = hp0[HH + k];
                    ulonglong2 gA = hp1[k], gB = hp1[HH + k];
                    aIF[0] = fma2(wIF[k], hA.x, fma2(ws.x, gA.x, aIF[0]));
                    aGO[0] = fma2(wGO[k], hA.x, fma2(ws.y, gA.x, aGO[0]));
                    aIF[1] = fma2(wIF[k], hA.y, fma2(ws.x, gA.y, aIF[1]));
                    aGO[1] = fma2(wGO[k], hA.y, fma2(ws.y, gA.y, aGO[1]));
                    aIF[2] = fma2(wIF[k], hB.x, fma2(ws.x, gB.x, aIF[2]));
                    aGO[2] = fma2(wGO[k], hB.x, fma2(ws.y, gB.x, aGO[2]));
                    aIF[3] = fma2(wIF[k], hB.y, fma2(ws.x, gB.y, aIF[3]));
                    aGO[3] = fma2(wGO[k], hB.y, fma2(ws.y, gB.y, aGO[3]));
                }
                float hn[4];
                #pragma unroll
                for (int e = 0; e < 4; e++) {
                    float ui, uf, ug, uo;
                    upk2(aIF[e], ui, uf); upk2(aGO[e], ug, uo);
                    float ig = sigf(ui), fg = sigf(uf), gg = tanh_fast(ug), og = sigf(uo);
                    float c = fmaf(fg, c1v[e], ig * gg);
                    c1v[e] = c;
                    hn[e] = og * tanh_fast(c);
                    h1s[e] = hn[e];
                }
                __syncwarp();   // all lanes done reading h1buf before overwrite
                float4* wp = h1buf[half];
                if (lane < HH) {
                    wp[jj]      = make_float4(hn[0], hn[0], hn[1], hn[1]);
                    wp[HH + jj] = make_float4(hn[2], hn[2], hn[3], hn[3]);
                }
            }
        }
        __syncthreads();
    }

    // ================= FC head: w1 (elems 0-3), w2 (elems 4-7) =================
    if (wid > 0) {
        const unsigned FULL = 0xffffffffu;
        const int eo = half * 4;
        float za[4], zb[4];
        #pragma unroll
        for (int e = 0; e < 4; e++) { za[e] = bfc1[lane]; zb[e] = bfc1[lane + 32]; }
        for (int k = 0; k < HH; k++) {
            float wa  = Wfc1[lane * HH + k];
            float wbv = Wfc1[(lane + 32) * HH + k];
            #pragma unroll
            for (int e = 0; e < 4; e++) {
                float hk = __shfl_sync(FULL, h1s[e], k);
                za[e] = fmaf(wa, hk, za[e]);
                zb[e] = fmaf(wbv, hk, zb[e]);
            }
        }
        #pragma unroll
        for (int e = 0; e < 4; e++) { za[e] = fmaxf(za[e], 0.f); zb[e] = fmaxf(zb[e], 0.f); }

        float z2[4];
        #pragma unroll
        for (int e = 0; e < 4; e++) z2[e] = bfc2[lane];
        for (int k = 0; k < 32; k++) {
            float w1v = Wfc2[lane * 64 + k];
            float w2v = Wfc2[lane * 64 + 32 + k];
            #pragma unroll
            for (int e = 0; e < 4; e++) {
                float zak = __shfl_sync(FULL, za[e], k);
                float zbk = __shfl_sync(FULL, zb[e], k);
                z2[e] = fmaf(w1v, zak, fmaf(w2v, zbk, z2[e]));
            }
        }
        float w3 = Wfc3[lane];
        float b3 = bfc3[0];
        #pragma unroll
        for (int e = 0; e < 4; e++) {
            float pr = w3 * fmaxf(z2[e], 0.f);
            #pragma unroll
            for (int off = 16; off; off >>= 1) pr += __shfl_xor_sync(FULL, pr, off);
            if (lane == 0) out[wb + eo + e] = sigf(pr + b3);
        }
    }
}

extern "C" void kernel_launch(void* const* d_in, const int* in_sizes, int n_in,
                              void* d_out, int out_size)
{
    const float* x    = (const float*)d_in[0];
    const float* Wih0 = (const float*)d_in[1];
    const float* Whh0 = (const float*)d_in[2];
    const float* bih0 = (const float*)d_in[3];
    const float* bhh0 = (const float*)d_in[4];
    const float* Wih1 = (const float*)d_in[5];
    const float* Whh1 = (const float*)d_in[6];
    const float* bih1 = (const float*)d_in[7];
    const float* bhh1 = (const float*)d_in[8];
    const float* Wfc1 = (const float*)d_in[9];
    const float* bfc1 = (const float*)d_in[10];
    const float* Wfc2 = (const float*)d_in[11];
    const float* bfc2 = (const float*)d_in[12];
    const float* Wfc3 = (const float*)d_in[13];
    const float* bfc3 = (const float*)d_in[14];
    float* out = (float*)d_out;

    int B = in_sizes[0] / (TT * INP);   // 8192
    int blocks = (B + NB - 1) / NB;     // 1024 teams

    stacked_lstm_kernel<<<blocks, NTHR>>>(x,
        Wih0, Whh0, bih0, bhh0,
        Wih1, Whh1, bih1, bhh1,
        Wfc1, bfc1, Wfc2, bfc2, Wfc3, bfc3,
        out, B);
}

// round 7
// speedup vs baseline: 1.1733x; 1.0594x over previous
#include <cuda_runtime.h>

#define TT   256
#define HH   30
#define INP  3
#define NB   4            // batch elements per warp
#define WPB  4            // warps per block (128 threads)

typedef unsigned long long ull;

// ---- f32x2 packed helpers (sm_103a) ----
__device__ __forceinline__ ull fma2(ull a, ull b, ull c) {
    ull d; asm("fma.rn.f32x2 %0,%1,%2,%3;" : "=l"(d) : "l"(a), "l"(b), "l"(c)); return d;
}
__device__ __forceinline__ ull pk2(float lo, float hi) {
    ull r; asm("mov.b64 %0,{%1,%2};" : "=l"(r) : "f"(lo), "f"(hi)); return r;
}
__device__ __forceinline__ void upk2(ull v, float& lo, float& hi) {
    asm("mov.b64 {%0,%1},%2;" : "=f"(lo), "=f"(hi) : "l"(v));
}

// ---- MUFU.TANH-based activations (1 MUFU each) ----
__device__ __forceinline__ float tanh_mufu(float x) {
    float r; asm("tanh.approx.f32 %0, %1;" : "=f"(r) : "f"(x)); return r;
}
__device__ __forceinline__ float sig_mufu(float x) {
    // sigmoid(x) = 0.5*tanh(0.5x) + 0.5
    return fmaf(0.5f, tanh_mufu(0.5f * x), 0.5f);
}

// Shared layout (floats):
//   sW0  : 900 float4  -> [k*30+j] = (wi,wf,wg,wo) of Whh0
//   sWi1 : 900 float4  -> Wih1
//   sWh1 : 900 float4  -> Whh1
//   hb   : WPB warps * 480 floats
//          layer0: 2 groups * 30 float4  [g*30+k] = (h_{2g},h_{2g},h_{2g+1},h_{2g+1})
//          layer1: same, at +240 floats
#define SMEM_FLOATS (3*900*4 + WPB*480)

__global__ void __launch_bounds__(32*WPB, 4)
stacked_lstm_kernel(const float* __restrict__ x,
                    const float* __restrict__ Wih0, const float* __restrict__ Whh0,
                    const float* __restrict__ bih0, const float* __restrict__ bhh0,
                    const float* __restrict__ Wih1, const float* __restrict__ Whh1,
                    const float* __restrict__ bih1, const float* __restrict__ bhh1,
                    const float* __restrict__ Wfc1, const float* __restrict__ bfc1,
                    const float* __restrict__ Wfc2, const float* __restrict__ bfc2,
                    const float* __restrict__ Wfc3, const float* __restrict__ bfc3,
                    float* __restrict__ out, int B)
{
    extern __shared__ float smem[];
    float4* sW0  = (float4*)smem;
    float4* sWi1 = sW0  + 900;
    float4* sWh1 = sWi1 + 900;
    float*  hbAll = (float*)(sWh1 + 900);

    const int tid = threadIdx.x;
    const int nthr = 32 * WPB;

    // Fill transposed, gate-interleaved weights: src row = g*30+j, col k.
    for (int idx = tid; idx < 3600; idx += nthr) {
        int row = idx / HH, k = idx % HH;
        int g = row / HH, j = row % HH;
        ((float*)&sW0 [k*HH + j])[g] = Whh0[idx];
        ((float*)&sWi1[k*HH + j])[g] = Wih1[idx];
        ((float*)&sWh1[k*HH + j])[g] = Whh1[idx];
    }
    for (int idx = tid; idx < WPB*480; idx += nthr) hbAll[idx] = 0.0f;
    __syncthreads();

    const int wib  = tid >> 5;
    const int lane = tid & 31;
    const int jj   = lane < HH ? lane : HH - 1;   // lanes 30,31 duplicate unit 29
    const int warp = blockIdx.x * WPB + wib;
    const long wb  = (long)warp * NB;
    if (wb >= B) return;

    float* hb = hbAll + wib * 480;
    const ulonglong2* w0p  = (const ulonglong2*)sW0;
    const ulonglong2* wi1p = (const ulonglong2*)sWi1;
    const ulonglong2* wh1p = (const ulonglong2*)sWh1;
    const ulonglong2* hp0  = (const ulonglong2*)hb;        // layer0 h, [g*30+k]
    const ulonglong2* hp1  = hp0 + 60;                     // layer1 h
    float4* st0 = (float4*)hb;
    float4* st1 = (float4*)(hb + 240);

    // Per-lane constants (gate pairs: IF = (i,f), GO = (g,o))
    const ull b0IF = pk2(bih0[jj]      + bhh0[jj],      bih0[jj + 30] + bhh0[jj + 30]);
    const ull b0GO = pk2(bih0[jj + 60] + bhh0[jj + 60], bih0[jj + 90] + bhh0[jj + 90]);
    const ull b1IF = pk2(bih1[jj]      + bhh1[jj],      bih1[jj + 30] + bhh1[jj + 30]);
    const ull b1GO = pk2(bih1[jj + 60] + bhh1[jj + 60], bih1[jj + 90] + bhh1[jj + 90]);
    ull wIF[INP], wGO[INP];
    #pragma unroll
    for (int c = 0; c < INP; c++) {
        wIF[c] = pk2(Wih0[jj*INP + c],        Wih0[(jj+30)*INP + c]);
        wGO[c] = pk2(Wih0[(jj+60)*INP + c],   Wih0[(jj+90)*INP + c]);
    }

    float c0v[NB], c1v[NB], h1s[NB];
    #pragma unroll
    for (int e = 0; e < NB; e++) { c0v[e] = 0.f; c1v[e] = 0.f; h1s[e] = 0.f; }

    const float* xbase = x + (size_t)wb * TT * INP;
    ull aIF[NB], aGO[NB];

    // Prefetch x[t=0]
    float xv[NB][INP];
    #pragma unroll
    for (int e = 0; e < NB; e++) {
        const float* xp = xbase + (size_t)e * TT * INP;
        xv[e][0] = xp[0]; xv[e][1] = xp[1]; xv[e][2] = xp[2];
    }

    for (int t = 0; t < TT; t++) {
        // ---- x contribution from prefetched registers ----
        #pragma unroll
        for (int e = 0; e < NB; e++) {
            ull d0 = pk2(xv[e][0], xv[e][0]);
            ull d1 = pk2(xv[e][1], xv[e][1]);
            ull d2 = pk2(xv[e][2], xv[e][2]);
            aIF[e] = fma2(wIF[0], d0, fma2(wIF[1], d1, fma2(wIF[2], d2, b0IF)));
            aGO[e] = fma2(wGO[0], d0, fma2(wGO[1], d1, fma2(wGO[2], d2, b0GO)));
        }
        // prefetch next step's x; LDG latency hidden behind both k-loops
        if (t + 1 < TT) {
            #pragma unroll
            for (int e = 0; e < NB; e++) {
                const float* xp = xbase + ((size_t)e * TT + (t + 1)) * INP;
                xv[e][0] = xp[0]; xv[e][1] = xp[1]; xv[e][2] = xp[2];
            }
        }

        // ---- layer 0: gates += Whh0 * h0 ----
        #pragma unroll
        for (int k = 0; k < HH; k++) {
            ulonglong2 w  = w0p[k*HH + jj];
            ulonglong2 hA = hp0[k], hB = hp0[30 + k];
            aIF[0] = fma2(w.x, hA.x, aIF[0]); aGO[0] = fma2(w.y, hA.x, aGO[0]);
            aIF[1] = fma2(w.x, hA.y, aIF[1]); aGO[1] = fma2(w.y, hA.y, aGO[1]);
            aIF[2] = fma2(w.x, hB.x, aIF[2]); aGO[2] = fma2(w.y, hB.x, aGO[2]);
            aIF[3] = fma2(w.x, hB.y, aIF[3]); aGO[3] = fma2(w.y, hB.y, aGO[3]);
        }

        float h0n[NB];
        #pragma unroll
        for (int e = 0; e < NB; e++) {
            float ui, uf, ug, uo;
            upk2(aIF[e], ui, uf); upk2(aGO[e], ug, uo);
            float ig = sig_mufu(ui), fg = sig_mufu(uf);
            float gg = tanh_mufu(ug), og = sig_mufu(uo);
            float c = fmaf(fg, c0v[e], ig * gg);
            c0v[e] = c;
            h0n[e] = og * tanh_mufu(c);
        }
        if (lane < HH) {
            st0[jj]      = make_float4(h0n[0], h0n[0], h0n[1], h0n[1]);
            st0[30 + jj] = make_float4(h0n[2], h0n[2], h0n[3], h0n[3]);
        }
        __syncwarp();

        // ---- layer 1: gates = b1 + Wih1*h0 + Whh1*h1 ----
        #pragma unroll
        for (int e = 0; e < NB; e++) { aIF[e] = b1IF; aGO[e] = b1GO; }
        #pragma unroll
        for (int k = 0; k < HH; k++) {
            ulonglong2 wi = wi1p[k*HH + jj];
            ulonglong2 wh = wh1p[k*HH + jj];
            ulonglong2 hA = hp0[k], hB = hp0[30 + k];
            ulonglong2 gA = hp1[k], gB = hp1[30 + k];
            aIF[0] = fma2(wi.x, hA.x, fma2(wh.x, gA.x, aIF[0]));
            aGO[0] = fma2(wi.y, hA.x, fma2(wh.y, gA.x, aGO[0]));
            aIF[1] = fma2(wi.x, hA.y, fma2(wh.x, gA.y, aIF[1]));
            aGO[1] = fma2(wi.y, hA.y, fma2(wh.y, gA.y, aGO[1]));
            aIF[2] = fma2(wi.x, hB.x, fma2(wh.x, gB.x, aIF[2]));
            aGO[2] = fma2(wi.y, hB.x, fma2(wh.y, gB.x, aGO[2]));
            aIF[3] = fma2(wi.x, hB.y, fma2(wh.x, gB.y, aIF[3]));
            aGO[3] = fma2(wi.y, hB.y, fma2(wh.y, gB.y, aGO[3]));
        }

        float h1n[NB];
        #pragma unroll
        for (int e = 0; e < NB; e++) {
            float ui, uf, ug, uo;
            upk2(aIF[e], ui, uf); upk2(aGO[e], ug, uo);
            float ig = sig_mufu(ui), fg = sig_mufu(uf);
            float gg = tanh_mufu(ug), og = sig_mufu(uo);
            float c = fmaf(fg, c1v[e], ig * gg);
            c1v[e] = c;
            h1n[e] = og * tanh_mufu(c);
            h1s[e] = h1n[e];
        }
        if (lane < HH) {
            st1[jj]      = make_float4(h1n[0], h1n[0], h1n[1], h1n[1]);
            st1[30 + jj] = make_float4(h1n[2], h1n[2], h1n[3], h1n[3]);
        }
        __syncwarp();
    }

    // ---------------- FC head (per warp, shuffles; one-time cost) ----------------
    const unsigned FULL = 0xffffffffu;
    float za[NB], zb[NB];
    #pragma unroll
    for (int e = 0; e < NB; e++) { za[e] = bfc1[lane]; zb[e] = bfc1[lane + 32]; }
    for (int k = 0; k < HH; k++) {
        float wa = Wfc1[lane * HH + k];
        float wbv = Wfc1[(lane + 32) * HH + k];
        #pragma unroll
        for (int e = 0; e < NB; e++) {
            float hk = __shfl_sync(FULL, h1s[e], k);
            za[e] = fmaf(wa, hk, za[e]);
            zb[e] = fmaf(wbv, hk, zb[e]);
        }
    }
    #pragma unroll
    for (int e = 0; e < NB; e++) { za[e] = fmaxf(za[e], 0.f); zb[e] = fmaxf(zb[e], 0.f); }

    float z2[NB];
    #pragma unroll
    for (int e = 0; e < NB; e++) z2[e] = bfc2[lane];
    for (int k = 0; k < 32; k++) {
        float w1 = Wfc2[lane * 64 + k];
        float w2 = Wfc2[lane * 64 + 32 + k];
        #pragma unroll
        for (int e = 0; e < NB; e++) {
            float zak = __shfl_sync(FULL, za[e], k);
            float zbk = __shfl_sync(FULL, zb[e], k);
            z2[e] = fmaf(w1, zak, fmaf(w2, zbk, z2[e]));
        }
    }
    float w3 = Wfc3[lane];
    float b3 = bfc3[0];
    #pragma unroll
    for (int e = 0; e < NB; e++) {
        float p = w3 * fmaxf(z2[e], 0.f);
        #pragma unroll
        for (int off = 16; off; off >>= 1) p += __shfl_xor_sync(FULL, p, off);
        if (lane == 0) out[wb + e] = sig_mufu(p + b3);
    }
}

extern "C" void kernel_launch(void* const* d_in, const int* in_sizes, int n_in,
                              void* d_out, int out_size)
{
    const float* x    = (const float*)d_in[0];
    const float* Wih0 = (const float*)d_in[1];
    const float* Whh0 = (const float*)d_in[2];
    const float* bih0 = (const float*)d_in[3];
    const float* bhh0 = (const float*)d_in[4];
    const float* Wih1 = (const float*)d_in[5];
    const float* Whh1 = (const float*)d_in[6];
    const float* bih1 = (const float*)d_in[7];
    const float* bhh1 = (const float*)d_in[8];
    const float* Wfc1 = (const float*)d_in[9];
    const float* bfc1 = (const float*)d_in[10];
    const float* Wfc2 = (const float*)d_in[11];
    const float* bfc2 = (const float*)d_in[12];
    const float* Wfc3 = (const float*)d_in[13];
    const float* bfc3 = (const float*)d_in[14];
    float* out = (float*)d_out;

    int B = in_sizes[0] / (TT * INP);                 // 8192
    int warps = (B + NB - 1) / NB;                    // 2048
    int blocks = (warps + WPB - 1) / WPB;             // 512

    size_t smem_bytes = SMEM_FLOATS * sizeof(float);  // ~50.9 KB
    cudaFuncSetAttribute(stacked_lstm_kernel,
                         cudaFuncAttributeMaxDynamicSharedMemorySize,
                         (int)smem_bytes);

    stacked_lstm_kernel<<<blocks, 32*WPB, smem_bytes>>>(x,
        Wih0, Whh0, bih0, bhh0,
        Wih1, Whh1, bih1, bhh1,
        Wfc1, bfc1, Wfc2, bfc2, Wfc3, bfc3,
        out, B);
}

// round 10
// speedup vs baseline: 2.1523x; 1.8344x over previous
#include <cuda_runtime.h>
#include <cuda_bf16.h>
#include <cstdint>

#define TT   256
#define HH   30
#define INP  3
#define ROWS 64
#define NTHR 256
#define NK0  7              // K0 = 112
#define NK1  12             // K1 = 192

#define A0STR 120           // bf16 per A0 row (60 words: conflict-free)
#define A1STR 200           // bf16 per A1 row (100 words: conflict-free)
#define A0ROWB (A0STR*2)
#define A1ROWB (A1STR*2)
#define A0BUFB (ROWS*A0ROWB)   // 15360
#define A1BUFB (ROWS*A1ROWB)   // 25600

#define SM_BF   0
#define NTILE0  (NK0*15)                 // 105 layer0 tiles
#define NTILET  (NTILE0 + NK1*15)        // 285 total
#define BF_SZ   (NTILET*256)             // 72960 bytes of B fragments
#define SM_A0   BF_SZ
#define SM_A1   (SM_A0 + 2*A0BUFB)       // 103680
#define SM_FC   (SM_A1 + 2*A1BUFB)       // 154880
#define SM_TOTAL (SM_FC + 4097*4)        // 171268

__device__ __forceinline__ float tanh_mufu(float x){ float r; asm("tanh.approx.f32 %0,%1;":"=f"(r):"f"(x)); return r; }
__device__ __forceinline__ float sig_mufu(float x){ return fmaf(0.5f, tanh_mufu(0.5f*x), 0.5f); }
__device__ __forceinline__ uint32_t pkbf(float lo, float hi){
    uint32_t r; asm("cvt.rn.bf16x2.f32 %0,%1,%2;":"=r"(r):"f"(hi),"f"(lo)); return r;  // lo->[15:0], hi->[31:16]
}
__device__ __forceinline__ void mma16816(float d[4], const uint32_t a[4], uint32_t b0, uint32_t b1){
    asm volatile("mma.sync.aligned.m16n8k16.row.col.f32.bf16.bf16.f32 "
        "{%0,%1,%2,%3},{%4,%5,%6,%7},{%8,%9},{%0,%1,%2,%3};"
        : "+f"(d[0]),"+f"(d[1]),"+f"(d[2]),"+f"(d[3])
        : "r"(a[0]),"r"(a[1]),"r"(a[2]),"r"(a[3]),"r"(b0),"r"(b1));
}
__device__ __forceinline__ float cellh(float gi, float gf, float gg, float go, float& c){
    float i_=sig_mufu(gi), f_=sig_mufu(gf), g_=tanh_mufu(gg), o_=sig_mufu(go);
    c = fmaf(f_, c, i_*g_);
    return o_ * tanh_mufu(c);
}
__device__ __forceinline__ float bhi(float w){ return __bfloat162float(__float2bfloat16(w)); }

// B element (k, gate-row r) for layer0 / layer1, matching the A k-layouts.
__device__ float b0v(int k, int r, const float* Wih0, const float* Whh0,
                     const float* bih0, const float* bhh0){
    if (k < 2)   { float b=bih0[r]+bhh0[r]; float h=bhi(b); return k==0? h : b-h; }
    if (k < 5)   { float w=Wih0[r*INP + (k-2)]; return bhi(w); }
    if (k < 8)   { float w=Wih0[r*INP + (k-5)]; return bhi(w); }
    if (k < 11)  { float w=Wih0[r*INP + (k-8)]; return w - bhi(w); }
    if (k < 12)  return 0.f;
    if (k < 42)  { float w=Whh0[r*HH + (k-12)]; return bhi(w); }
    if (k < 72)  { float w=Whh0[r*HH + (k-42)]; return bhi(w); }
    if (k < 102) { float w=Whh0[r*HH + (k-72)]; return w - bhi(w); }
    return 0.f;
}
__device__ float b1v(int k, int r, const float* Wih1, const float* Whh1,
                     const float* bih1, const float* bhh1){
    if (k < 2)   { float b=bih1[r]+bhh1[r]; float h=bhi(b); return k==0? h : b-h; }
    if (k < 32)  { float w=Wih1[r*HH + (k-2)];  return bhi(w); }
    if (k < 62)  { float w=Wih1[r*HH + (k-32)]; return bhi(w); }
    if (k < 92)  { float w=Wih1[r*HH + (k-62)]; return w - bhi(w); }
    if (k < 122) { float w=Whh1[r*HH + (k-92)];  return bhi(w); }
    if (k < 152) { float w=Whh1[r*HH + (k-122)]; return bhi(w); }
    if (k < 182) { float w=Whh1[r*HH + (k-152)]; return w - bhi(w); }
    return 0.f;
}

__global__ void __launch_bounds__(NTHR)
stacked_lstm_hmma(const float* __restrict__ x,
                  const float* __restrict__ Wih0, const float* __restrict__ Whh0,
                  const float* __restrict__ bih0, const float* __restrict__ bhh0,
                  const float* __restrict__ Wih1, const float* __restrict__ Whh1,
                  const float* __restrict__ bih1, const float* __restrict__ bhh1,
                  const float* __restrict__ Wfc1, const float* __restrict__ bfc1,
                  const float* __restrict__ Wfc2, const float* __restrict__ bfc2,
                  const float* __restrict__ Wfc3, const float* __restrict__ bfc3,
                  float* __restrict__ out, int B)
{
    extern __shared__ char sm[];
    const int tid  = threadIdx.x;
    const int wid  = tid >> 5;
    const int lane = tid & 31;
    const int grp  = lane >> 2;     // fragment row group
    const int tig  = lane & 3;      // thread in group
    const int rt   = wid >> 1;      // row tile 0..3
    const int nh   = wid & 1;       // N half
    const int ntb  = nh * 8;        // n-tile base
    const int NTn  = nh ? 7 : 8;
    const int row0 = rt*16 + grp;
    const int rowE = row0 + ((tig & 1) << 3);   // row this thread's cell belongs to
    const int xrow = tid >> 2, xc = tid & 3;
    const bool xact = (xc < 3);
    const unsigned FULL = 0xffffffffu;

    // ================= preamble =================
    // zero A0 + A1 (contiguous)
    for (int i = tid; i < (2*A0BUFB + 2*A1BUFB)/4; i += NTHR)
        ((uint32_t*)(sm + SM_A0))[i] = 0u;

    // pre-scatter B fragments (uint2 per lane per tile)
    uint2* bfr = (uint2*)(sm + SM_BF);
    for (int idx = tid; idx < NTILET*32; idx += NTHR) {
        int ln = idx & 31, gt = idx >> 5;
        int layer = (gt >= NTILE0);
        int lt = layer ? gt - NTILE0 : gt;
        int kt = lt / 15, nt = lt % 15;
        int n  = nt*8 + (ln >> 2);
        int j  = n >> 2, g = n & 3;
        int r  = g*HH + j;
        int k0 = kt*16 + 2*(ln & 3);
        float v00, v01, v10, v11;
        if (!layer) {
            v00=b0v(k0,r,Wih0,Whh0,bih0,bhh0);   v01=b0v(k0+1,r,Wih0,Whh0,bih0,bhh0);
            v10=b0v(k0+8,r,Wih0,Whh0,bih0,bhh0); v11=b0v(k0+9,r,Wih0,Whh0,bih0,bhh0);
        } else {
            v00=b1v(k0,r,Wih1,Whh1,bih1,bhh1);   v01=b1v(k0+1,r,Wih1,Whh1,bih1,bhh1);
            v10=b1v(k0+8,r,Wih1,Whh1,bih1,bhh1); v11=b1v(k0+9,r,Wih1,Whh1,bih1,bhh1);
        }
        bfr[gt*32 + ln] = make_uint2(pkbf(v00, v01), pkbf(v10, v11));
    }
    // FC weights to smem
    float* fcs = (float*)(sm + SM_FC);
    for (int i = tid; i < 64*HH; i += NTHR) fcs[i] = Wfc1[i];
    for (int i = tid; i < 64; i += NTHR)    fcs[1920 + i] = bfc1[i];
    for (int i = tid; i < 32*64; i += NTHR) fcs[1984 + i] = Wfc2[i];
    for (int i = tid; i < 32; i += NTHR) { fcs[4032 + i] = bfc2[i]; fcs[4064 + i] = Wfc3[i]; }
    if (tid == 0) fcs[4096] = bfc3[0];
    __syncthreads();

    // bias ones (col word 0 of every row, both buffers, both A matrices)
    if (tid < 2*ROWS) {
        int b = tid >> 6, row = tid & 63;
        *(uint32_t*)(sm + SM_A0 + b*A0BUFB + row*A0ROWB) = 0x3F803F80u;
        *(uint32_t*)(sm + SM_A1 + b*A1BUFB + row*A1ROWB) = 0x3F803F80u;
    }
    // x(0) into A0 buf0
    const float* xptr = x + ((size_t)blockIdx.x*ROWS + xrow)*TT*INP + xc;
    if (xact) {
        float xv = xptr[0];
        __nv_bfloat16 hi = __float2bfloat16(xv);
        __nv_bfloat16 lo = __float2bfloat16(xv - __bfloat162float(hi));
        __nv_bfloat16* an = (__nv_bfloat16*)(sm + SM_A0 + xrow*A0ROWB);
        an[2+xc] = hi; an[5+xc] = lo; an[8+xc] = hi;
    }
    __syncthreads();

    // ================= recurrence =================
    float cst0[8], cst1[8];
    #pragma unroll
    for (int i = 0; i < 8; i++) { cst0[i] = 0.f; cst1[i] = 0.f; }

    for (int t = 0; t < TT; t++) {
        const int rb = t & 1, wbuf = rb ^ 1;

        // ---- L0 MMA: D = A0[rb] x B0 ----
        float acc[8][4];
        #pragma unroll
        for (int n2 = 0; n2 < 8; n2++)
            { acc[n2][0]=0.f; acc[n2][1]=0.f; acc[n2][2]=0.f; acc[n2][3]=0.f; }
        {
            const char* ab = sm + SM_A0 + rb*A0BUFB + row0*A0ROWB;
            #pragma unroll
            for (int kt = 0; kt < NK0; kt++) {
                uint32_t a[4];
                const char* p = ab + kt*32 + tig*4;
                a[0] = *(const uint32_t*)(p);
                a[1] = *(const uint32_t*)(p + 8*A0ROWB);
                a[2] = *(const uint32_t*)(p + 16);
                a[3] = *(const uint32_t*)(p + 8*A0ROWB + 16);
                #pragma unroll
                for (int n2 = 0; n2 < 8; n2++) {
                    if (n2 < NTn) {
                        uint2 bf = bfr[(kt*15 + ntb + n2)*32 + lane];
                        mma16816(acc[n2], a, bf.x, bf.y);
                    }
                }
            }
        }
        // prefetch next x
        float xn = 0.f;
        if (t + 1 < TT && xact) xn = xptr[(size_t)(t+1)*INP];

        // ---- L0 epilogue: gates -> h0; write A0[wbuf] + A1[rb] ----
        #pragma unroll
        for (int n2 = 0; n2 < 8; n2++) {
            if (n2 < NTn) {
                float p0 = __shfl_xor_sync(FULL, acc[n2][0], 1);
                float p1 = __shfl_xor_sync(FULL, acc[n2][1], 1);
                float p2 = __shfl_xor_sync(FULL, acc[n2][2], 1);
                float p3 = __shfl_xor_sync(FULL, acc[n2][3], 1);
                float gi, gf, gg, go;
                if ((tig & 1) == 0) { gi = acc[n2][0]; gf = acc[n2][1]; gg = p0; go = p1; }
                else                { gi = p2;         gf = p3;         gg = acc[n2][2]; go = acc[n2][3]; }
                float h = cellh(gi, gf, gg, go, cst0[n2]);
                __nv_bfloat16 hi = __float2bfloat16(h);
                __nv_bfloat16 lo = __float2bfloat16(h - __bfloat162float(hi));
                int j = 2*(ntb + n2) + (tig >> 1);
                __nv_bfloat16* an = (__nv_bfloat16*)(sm + SM_A0 + wbuf*A0BUFB + rowE*A0ROWB);
                an[12+j] = hi; an[42+j] = lo; an[72+j] = hi;
                __nv_bfloat16* ac = (__nv_bfloat16*)(sm + SM_A1 + rb*A1BUFB + rowE*A1ROWB);
                ac[2+j] = hi; ac[32+j] = lo; ac[62+j] = hi;
            }
        }
        // store next x into A0[wbuf]
        if (t + 1 < TT && xact) {
            __nv_bfloat16 hi = __float2bfloat16(xn);
            __nv_bfloat16 lo = __float2bfloat16(xn - __bfloat162float(hi));
            __nv_bfloat16* an = (__nv_bfloat16*)(sm + SM_A0 + wbuf*A0BUFB + xrow*A0ROWB);
            an[2+xc] = hi; an[5+xc] = lo; an[8+xc] = hi;
        }
        __syncthreads();   // h0(t) visible in A1[rb]

        // ---- L1 MMA: D = A1[rb] x B1 ----
        #pragma unroll
        for (int n2 = 0; n2 < 8; n2++)
            { acc[n2][0]=0.f; acc[n2][1]=0.f; acc[n2][2]=0.f; acc[n2][3]=0.f; }
        {
            const char* ab = sm + SM_A1 + rb*A1BUFB + row0*A1ROWB;
            #pragma unroll
            for (int kt = 0; kt < NK1; kt++) {
                uint32_t a[4];
                const char* p = ab + kt*32 + tig*4;
                a[0] = *(const uint32_t*)(p);
                a[1] = *(const uint32_t*)(p + 8*A1ROWB);
                a[2] = *(const uint32_t*)(p + 16);
                a[3] = *(const uint32_t*)(p + 8*A1ROWB + 16);
                #pragma unroll
                for (int n2 = 0; n2 < 8; n2++) {
                    if (n2 < NTn) {
                        uint2 bf = bfr[(NTILE0 + kt*15 + ntb + n2)*32 + lane];
                        mma16816(acc[n2], a, bf.x, bf.y);
                    }
                }
            }
        }
        // ---- L1 epilogue: gates -> h1; write A1[wbuf] ----
        #pragma unroll
        for (int n2 = 0; n2 < 8; n2++) {
            if (n2 < NTn) {
                float p0 = __shfl_xor_sync(FULL, acc[n2][0], 1);
                float p1 = __shfl_xor_sync(FULL, acc[n2][1], 1);
                float p2 = __shfl_xor_sync(FULL, acc[n2][2], 1);
                float p3 = __shfl_xor_sync(FULL, acc[n2][3], 1);
                float gi, gf, gg, go;
                if ((tig & 1) == 0) { gi = acc[n2][0]; gf = acc[n2][1]; gg = p0; go = p1; }
                else                { gi = p2;         gf = p3;         gg = acc[n2][2]; go = acc[n2][3]; }
                float h = cellh(gi, gf, gg, go, cst1[n2]);
                __nv_bfloat16 hi = __float2bfloat16(h);
                __nv_bfloat16 lo = __float2bfloat16(h - __bfloat162float(hi));
                int j = 2*(ntb + n2) + (tig >> 1);
                __nv_bfloat16* an = (__nv_bfloat16*)(sm + SM_A1 + wbuf*A1BUFB + rowE*A1ROWB);
                an[92+j] = hi; an[122+j] = lo; an[152+j] = hi;
            }
        }
        __syncthreads();   // A0[wbuf]/A1[wbuf] ready for next step
    }

    // ================= FC head (threads 0..63; h1 final is in A1 buf0) =================
    if (tid < ROWS) {
        const __nv_bfloat16* af = (const __nv_bfloat16*)(sm + SM_A1 + tid*A1ROWB);
        float h1f[HH];
        #pragma unroll
        for (int u = 0; u < HH; u++)
            h1f[u] = __bfloat162float(af[92+u]) + __bfloat162float(af[122+u]);

        float z2[32];
        #pragma unroll
        for (int o = 0; o < 32; o++) z2[o] = fcs[4032 + o];
        for (int k = 0; k < 64; k++) {
            float z = fcs[1920 + k];
            #pragma unroll
            for (int c = 0; c < HH; c++) z = fmaf(fcs[k*HH + c], h1f[c], z);
            z = fmaxf(z, 0.0f);
            #pragma unroll
            for (int o = 0; o < 32; o++) z2[o] = fmaf(fcs[1984 + o*64 + k], z, z2[o]);
        }
        float acc = fcs[4096];
        #pragma unroll
        for (int o = 0; o < 32; o++) acc = fmaf(fcs[4064 + o], fmaxf(z2[o], 0.0f), acc);
        out[(size_t)blockIdx.x*ROWS + tid] = __fdividef(1.0f, 1.0f + __expf(-acc));
    }
}

extern "C" void kernel_launch(void* const* d_in, const int* in_sizes, int n_in,
                              void* d_out, int out_size)
{
    const float* x    = (const float*)d_in[0];
    const float* Wih0 = (const float*)d_in[1];
    const float* Whh0 = (const float*)d_in[2];
    const float* bih0 = (const float*)d_in[3];
    const float* bhh0 = (const float*)d_in[4];
    const float* Wih1 = (const float*)d_in[5];
    const float* Whh1 = (const float*)d_in[6];
    const float* bih1 = (const float*)d_in[7];
    const float* bhh1 = (const float*)d_in[8];
    const float* Wfc1 = (const float*)d_in[9];
    const float* bfc1 = (const float*)d_in[10];
    const float* Wfc2 = (const float*)d_in[11];
    const float* bfc2 = (const float*)d_in[12];
    const float* Wfc3 = (const float*)d_in[13];
    const float* bfc3 = (const float*)d_in[14];
    float* out = (float*)d_out;

    int B = in_sizes[0] / (TT * INP);   // 8192
    int blocks = B / ROWS;              // 128

    cudaFuncSetAttribute(stacked_lstm_hmma,
                         cudaFuncAttributeMaxDynamicSharedMemorySize, SM_TOTAL);

    stacked_lstm_hmma<<<blocks, NTHR, SM_TOTAL>>>(x,
        Wih0, Whh0, bih0, bhh0,
        Wih1, Whh1, bih1, bhh1,
        Wfc1, bfc1, Wfc2, bfc2, Wfc3, bfc3,
        out, B);
}

// round 11
// speedup vs baseline: 2.1845x; 1.0150x over previous
#include <cuda_runtime.h>
#include <cuda_bf16.h>
#include <cstdint>

#define TT   256
#define HH   30
#define INP  3
#define ROWS 64
#define NTHR 512
#define NK0  7              // K0 = 112
#define NK1  12             // K1 = 192

#define A0STR 120           // bf16 per A0 row
#define A1STR 200           // bf16 per A1 row
#define A0ROWB (A0STR*2)
#define A1ROWB (A1STR*2)
#define A0BUFB (ROWS*A0ROWB)   // 15360
#define A1BUFB (ROWS*A1ROWB)   // 25600

#define SM_BF   0
#define NTILE0  (NK0*15)                 // 105 layer0 tiles
#define NTILET  (NTILE0 + NK1*15)        // 285 total
#define BF_SZ   (NTILET*256)             // 72960
#define SM_A0   BF_SZ
#define SM_A1   (SM_A0 + 2*A0BUFB)
#define SM_FC   (SM_A1 + 2*A1BUFB)
#define SM_TOTAL (SM_FC + 4097*4)        // 171268

__device__ __forceinline__ float tanh_mufu(float x){ float r; asm("tanh.approx.f32 %0,%1;":"=f"(r):"f"(x)); return r; }
__device__ __forceinline__ float sig_mufu(float x){ return fmaf(0.5f, tanh_mufu(0.5f*x), 0.5f); }
__device__ __forceinline__ uint32_t pkbf(float lo, float hi){
    uint32_t r; asm("cvt.rn.bf16x2.f32 %0,%1,%2;":"=r"(r):"f"(hi),"f"(lo)); return r;
}
__device__ __forceinline__ void mma16816(float d[4], const uint32_t a[4], uint32_t b0, uint32_t b1){
    asm volatile("mma.sync.aligned.m16n8k16.row.col.f32.bf16.bf16.f32 "
        "{%0,%1,%2,%3},{%4,%5,%6,%7},{%8,%9},{%0,%1,%2,%3};"
        : "+f"(d[0]),"+f"(d[1]),"+f"(d[2]),"+f"(d[3])
        : "r"(a[0]),"r"(a[1]),"r"(a[2]),"r"(a[3]),"r"(b0),"r"(b1));
}
__device__ __forceinline__ float cellh(float gi, float gf, float gg, float go, float& c){
    float i_=sig_mufu(gi), f_=sig_mufu(gf), g_=tanh_mufu(gg), o_=sig_mufu(go);
    c = fmaf(f_, c, i_*g_);
    return o_ * tanh_mufu(c);
}
__device__ __forceinline__ float bhi(float w){ return __bfloat162float(__float2bfloat16(w)); }

// B element (k, gate-row r) for layer0 / layer1, matching the A k-layouts.
__device__ float b0v(int k, int r, const float* Wih0, const float* Whh0,
                     const float* bih0, const float* bhh0){
    if (k < 2)   { float b=bih0[r]+bhh0[r]; float h=bhi(b); return k==0? h : b-h; }
    if (k < 5)   { float w=Wih0[r*INP + (k-2)]; return bhi(w); }
    if (k < 8)   { float w=Wih0[r*INP + (k-5)]; return bhi(w); }
    if (k < 11)  { float w=Wih0[r*INP + (k-8)]; return w - bhi(w); }
    if (k < 12)  return 0.f;
    if (k < 42)  { float w=Whh0[r*HH + (k-12)]; return bhi(w); }
    if (k < 72)  { float w=Whh0[r*HH + (k-42)]; return bhi(w); }
    if (k < 102) { float w=Whh0[r*HH + (k-72)]; return w - bhi(w); }
    return 0.f;
}
__device__ float b1v(int k, int r, const float* Wih1, const float* Whh1,
                     const float* bih1, const float* bhh1){
    if (k < 2)   { float b=bih1[r]+bhh1[r]; float h=bhi(b); return k==0? h : b-h; }
    if (k < 32)  { float w=Wih1[r*HH + (k-2)];  return bhi(w); }
    if (k < 62)  { float w=Wih1[r*HH + (k-32)]; return bhi(w); }
    if (k < 92)  { float w=Wih1[r*HH + (k-62)]; return w - bhi(w); }
    if (k < 122) { float w=Whh1[r*HH + (k-92)];  return bhi(w); }
    if (k < 152) { float w=Whh1[r*HH + (k-122)]; return bhi(w); }
    if (k < 182) { float w=Whh1[r*HH + (k-152)]; return w - bhi(w); }
    return 0.f;
}

__global__ void __launch_bounds__(NTHR, 1)
stacked_lstm_hmma(const float* __restrict__ x,
                  const float* __restrict__ Wih0, const float* __restrict__ Whh0,
                  const float* __restrict__ bih0, const float* __restrict__ bhh0,
                  const float* __restrict__ Wih1, const float* __restrict__ Whh1,
                  const float* __restrict__ bih1, const float* __restrict__ bhh1,
                  const float* __restrict__ Wfc1, const float* __restrict__ bfc1,
                  const float* __restrict__ Wfc2, const float* __restrict__ bfc2,
                  const float* __restrict__ Wfc3, const float* __restrict__ bfc3,
                  float* __restrict__ out, int B)
{
    extern __shared__ char sm[];
    const int tid  = threadIdx.x;
    const int wid  = tid >> 5;
    const int lane = tid & 31;
    const int grp  = lane >> 2;     // fragment row group
    const int tig  = lane & 3;      // thread in group
    const int rt   = wid >> 2;      // row tile 0..3
    const int nq   = wid & 3;       // N quarter 0..3
    const int ntb  = nq * 4;        // n-tile base
    const int NTn  = (nq == 3) ? 3 : 4;
    const int row0 = rt*16 + grp;
    const int rowE = row0 + ((tig & 1) << 3);
    const int xrow = tid >> 3, xc = tid & 7;
    const bool xact = (xc < 3);
    const unsigned FULL = 0xffffffffu;

    // ================= preamble =================
    for (int i = tid; i < (2*A0BUFB + 2*A1BUFB)/4; i += NTHR)
        ((uint32_t*)(sm + SM_A0))[i] = 0u;

    // pre-scatter B fragments
    uint2* bfr = (uint2*)(sm + SM_BF);
    for (int idx = tid; idx < NTILET*32; idx += NTHR) {
        int ln = idx & 31, gt = idx >> 5;
        int layer = (gt >= NTILE0);
        int lt = layer ? gt - NTILE0 : gt;
        int kt = lt / 15, nt = lt % 15;
        int n  = nt*8 + (ln >> 2);
        int j  = n >> 2, g = n & 3;
        int r  = g*HH + j;
        int k0 = kt*16 + 2*(ln & 3);
        float v00, v01, v10, v11;
        if (!layer) {
            v00=b0v(k0,r,Wih0,Whh0,bih0,bhh0);   v01=b0v(k0+1,r,Wih0,Whh0,bih0,bhh0);
            v10=b0v(k0+8,r,Wih0,Whh0,bih0,bhh0); v11=b0v(k0+9,r,Wih0,Whh0,bih0,bhh0);
        } else {
            v00=b1v(k0,r,Wih1,Whh1,bih1,bhh1);   v01=b1v(k0+1,r,Wih1,Whh1,bih1,bhh1);
            v10=b1v(k0+8,r,Wih1,Whh1,bih1,bhh1); v11=b1v(k0+9,r,Wih1,Whh1,bih1,bhh1);
        }
        bfr[gt*32 + ln] = make_uint2(pkbf(v00, v01), pkbf(v10, v11));
    }
    // FC weights to smem
    float* fcs = (float*)(sm + SM_FC);
    for (int i = tid; i < 64*HH; i += NTHR) fcs[i] = Wfc1[i];
    for (int i = tid; i < 64; i += NTHR)    fcs[1920 + i] = bfc1[i];
    for (int i = tid; i < 32*64; i += NTHR) fcs[1984 + i] = Wfc2[i];
    for (int i = tid; i < 32; i += NTHR) { fcs[4032 + i] = bfc2[i]; fcs[4064 + i] = Wfc3[i]; }
    if (tid == 0) fcs[4096] = bfc3[0];
    __syncthreads();

    // bias ones (word 0 of every row, both buffers, both A matrices)
    if (tid < 2*ROWS) {
        int b = tid >> 6, row = tid & 63;
        *(uint32_t*)(sm + SM_A0 + b*A0BUFB + row*A0ROWB) = 0x3F803F80u;
        *(uint32_t*)(sm + SM_A1 + b*A1BUFB + row*A1ROWB) = 0x3F803F80u;
    }
    // x(0) into A0 buf0
    const float* xptr = x + ((size_t)blockIdx.x*ROWS + xrow)*TT*INP + xc;
    if (xact) {
        float xv = xptr[0];
        __nv_bfloat16 hi = __float2bfloat16(xv);
        __nv_bfloat16 lo = __float2bfloat16(xv - __bfloat162float(hi));
        __nv_bfloat16* an = (__nv_bfloat16*)(sm + SM_A0 + xrow*A0ROWB);
        an[2+xc] = hi; an[5+xc] = lo; an[8+xc] = hi;
    }
    __syncthreads();

    // ================= recurrence =================
    float cst0[4], cst1[4];
    #pragma unroll
    for (int i = 0; i < 4; i++) { cst0[i] = 0.f; cst1[i] = 0.f; }

    for (int t = 0; t < TT; t++) {
        const int rb = t & 1, wbuf = rb ^ 1;

        // ---- L0 MMA ----
        float acc[4][4];
        #pragma unroll
        for (int n2 = 0; n2 < 4; n2++)
            { acc[n2][0]=0.f; acc[n2][1]=0.f; acc[n2][2]=0.f; acc[n2][3]=0.f; }
        {
            const char* ab = sm + SM_A0 + rb*A0BUFB + row0*A0ROWB;
            #pragma unroll
            for (int kt = 0; kt < NK0; kt++) {
                uint32_t a[4];
                const char* p = ab + kt*32 + tig*4;
                a[0] = *(const uint32_t*)(p);
                a[1] = *(const uint32_t*)(p + 8*A0ROWB);
                a[2] = *(const uint32_t*)(p + 16);
                a[3] = *(const uint32_t*)(p + 8*A0ROWB + 16);
                #pragma unroll
                for (int n2 = 0; n2 < 4; n2++) {
                    if (n2 < NTn) {
                        uint2 bf = bfr[(kt*15 + ntb + n2)*32 + lane];
                        mma16816(acc[n2], a, bf.x, bf.y);
                    }
                }
            }
        }
        // prefetch next x
        float xn = 0.f;
        if (t + 1 < TT && xact) xn = xptr[(size_t)(t+1)*INP];

        // ---- L0 epilogue ----
        #pragma unroll
        for (int n2 = 0; n2 < 4; n2++) {
            if (n2 < NTn) {
                float p0 = __shfl_xor_sync(FULL, acc[n2][0], 1);
                float p1 = __shfl_xor_sync(FULL, acc[n2][1], 1);
                float p2 = __shfl_xor_sync(FULL, acc[n2][2], 1);
                float p3 = __shfl_xor_sync(FULL, acc[n2][3], 1);
                float gi, gf, gg, go;
                if ((tig & 1) == 0) { gi = acc[n2][0]; gf = acc[n2][1]; gg = p0; go = p1; }
                else                { gi = p2;         gf = p3;         gg = acc[n2][2]; go = acc[n2][3]; }
                float h = cellh(gi, gf, gg, go, cst0[n2]);
                __nv_bfloat16 hi = __float2bfloat16(h);
                __nv_bfloat16 lo = __float2bfloat16(h - __bfloat162float(hi));
                int j = 2*(ntb + n2) + (tig >> 1);
                __nv_bfloat16* an = (__nv_bfloat16*)(sm + SM_A0 + wbuf*A0BUFB + rowE*A0ROWB);
                an[12+j] = hi; an[42+j] = lo; an[72+j] = hi;
                __nv_bfloat16* ac = (__nv_bfloat16*)(sm + SM_A1 + rb*A1BUFB + rowE*A1ROWB);
                ac[2+j] = hi; ac[32+j] = lo; ac[62+j] = hi;
            }
        }
        // store next x into A0[wbuf]
        if (t + 1 < TT && xact) {
            __nv_bfloat16 hi = __float2bfloat16(xn);
            __nv_bfloat16 lo = __float2bfloat16(xn - __bfloat162float(hi));
            __nv_bfloat16* an = (__nv_bfloat16*)(sm + SM_A0 + wbuf*A0BUFB + xrow*A0ROWB);
            an[2+xc] = hi; an[5+xc] = lo; an[8+xc] = hi;
        }
        __syncthreads();   // h0(t) visible in A1[rb]

        // ---- L1 MMA ----
        #pragma unroll
        for (int n2 = 0; n2 < 4; n2++)
            { acc[n2][0]=0.f; acc[n2][1]=0.f; acc[n2][2]=0.f; acc[n2][3]=0.f; }
        {
            const char* ab = sm + SM_A1 + rb*A1BUFB + row0*A1ROWB;
            #pragma unroll
            for (int kt = 0; kt < NK1; kt++) {
                uint32_t a[4];
                const char* p = ab + kt*32 + tig*4;
                a[0] = *(const uint32_t*)(p);
                a[1] = *(const uint32_t*)(p + 8*A1ROWB);
                a[2] = *(const uint32_t*)(p + 16);
                a[3] = *(const uint32_t*)(p + 8*A1ROWB + 16);
                #pragma unroll
                for (int n2 = 0; n2 < 4; n2++) {
                    if (n2 < NTn) {
                        uint2 bf = bfr[(NTILE0 + kt*15 + ntb + n2)*32 + lane];
                        mma16816(acc[n2], a, bf.x, bf.y);
                    }
                }
            }
        }
        // ---- L1 epilogue ----
        #pragma unroll
        for (int n2 = 0; n2 < 4; n2++) {
            if (n2 < NTn) {
                float p0 = __shfl_xor_sync(FULL, acc[n2][0], 1);
                float p1 = __shfl_xor_sync(FULL, acc[n2][1], 1);
                float p2 = __shfl_xor_sync(FULL, acc[n2][2], 1);
                float p3 = __shfl_xor_sync(FULL, acc[n2][3], 1);
                float gi, gf, gg, go;
                if ((tig & 1) == 0) { gi = acc[n2][0]; gf = acc[n2][1]; gg = p0; go = p1; }
                else                { gi = p2;         gf = p3;         gg = acc[n2][2]; go = acc[n2][3]; }
                float h = cellh(gi, gf, gg, go, cst1[n2]);
                __nv_bfloat16 hi = __float2bfloat16(h);
                __nv_bfloat16 lo = __float2bfloat16(h - __bfloat162float(hi));
                int j = 2*(ntb + n2) + (tig >> 1);
                __nv_bfloat16* an = (__nv_bfloat16*)(sm + SM_A1 + wbuf*A1BUFB + rowE*A1ROWB);
                an[92+j] = hi; an[122+j] = lo; an[152+j] = hi;
            }
        }
        __syncthreads();
    }

    // ================= FC head (threads 0..63; h1 final in A1 buf0) =================
    if (tid < ROWS) {
        const __nv_bfloat16* af = (const __nv_bfloat16*)(sm + SM_A1 + tid*A1ROWB);
        float h1f[HH];
        #pragma unroll
        for (int u = 0; u < HH; u++)
            h1f[u] = __bfloat162float(af[92+u]) + __bfloat162float(af[122+u]);

        float z2[32];
        #pragma unroll
        for (int o = 0; o < 32; o++) z2[o] = fcs[4032 + o];
        for (int k = 0; k < 64; k++) {
            float z = fcs[1920 + k];
            #pragma unroll
            for (int c = 0; c < HH; c++) z = fmaf(fcs[k*HH + c], h1f[c], z);
            z = fmaxf(z, 0.0f);
            #pragma unroll
            for (int o = 0; o < 32; o++) z2[o] = fmaf(fcs[1984 + o*64 + k], z, z2[o]);
        }
        float acc = fcs[4096];
        #pragma unroll
        for (int o = 0; o < 32; o++) acc = fmaf(fcs[4064 + o], fmaxf(z2[o], 0.0f), acc);
        out[(size_t)blockIdx.x*ROWS + tid] = __fdividef(1.0f, 1.0f + __expf(-acc));
    }
}

extern "C" void kernel_launch(void* const* d_in, const int* in_sizes, int n_in,
                              void* d_out, int out_size)
{
    const float* x    = (const float*)d_in[0];
    const float* Wih0 = (const float*)d_in[1];
    const float* Whh0 = (const float*)d_in[2];
    const float* bih0 = (const float*)d_in[3];
    const float* bhh0 = (const float*)d_in[4];
    const float* Wih1 = (const float*)d_in[5];
    const float* Whh1 = (const float*)d_in[6];
    const float* bih1 = (const float*)d_in[7];
    const float* bhh1 = (const float*)d_in[8];
    const float* Wfc1 = (const float*)d_in[9];
    const float* bfc1 = (const float*)d_in[10];
    const float* Wfc2 = (const float*)d_in[11];
    const float* bfc2 = (const float*)d_in[12];
    const float* Wfc3 = (const float*)d_in[13];
    const float* bfc3 = (const float*)d_in[14];
    float* out = (float*)d_out;

    int B = in_sizes[0] / (TT * INP);   // 8192
    int blocks = B / ROWS;              // 128

    cudaFuncSetAttribute(stacked_lstm_hmma,
                         cudaFuncAttributeMaxDynamicSharedMemorySize, SM_TOTAL);

    stacked_lstm_hmma<<<blocks, NTHR, SM_TOTAL>>>(x,
        Wih0, Whh0, bih0, bhh0,
        Wih1, Whh1, bih1, bhh1,
        Wfc1, bfc1, Wfc2, bfc2, Wfc3, bfc3,
        out, B);
}

// round 12
// speedup vs baseline: 2.9731x; 1.3610x over previous
#include <cuda_runtime.h>
#include <cuda_fp16.h>
#include <cstdint>

#define TT   256
#define HH   30
#define INP  3
#define ROWS 64
#define NTHR 512
#define NK0  5              // K0 = 80
#define NK1  8              // K1 = 128

#define A0STR 88            // fp16 per A0 row (44 words: conflict-free)
#define A1STR 136           // fp16 per A1 row (68 words: conflict-free)
#define A0ROWB (A0STR*2)
#define A1ROWB (A1STR*2)
#define A0BUFB (ROWS*A0ROWB)   // 11264
#define A1BUFB (ROWS*A1ROWB)   // 17408

#define SM_BF   0
#define NTILE0  (NK0*15)                 // 75 layer0 tiles
#define NTILET  (NTILE0 + NK1*15)        // 195 total
#define BF_SZ   (NTILET*256)             // 49920
#define SM_A0   BF_SZ
#define SM_A1   (SM_A0 + 2*A0BUFB)       // 72448
#define SM_FC   (SM_A1 + 2*A1BUFB)       // 107264
#define SM_TOTAL (SM_FC + 4097*4)        // 123652
// fp32 h1 stash for FC head aliases the B0 fragment region (dead at phase TT)

__device__ __forceinline__ float tanh_mufu(float x){ float r; asm("tanh.approx.f32 %0,%1;":"=f"(r):"f"(x)); return r; }
__device__ __forceinline__ float sig_mufu(float x){ return fmaf(0.5f, tanh_mufu(0.5f*x), 0.5f); }
__device__ __forceinline__ uint32_t pkhf(float a, float b){
    __half2 h = __halves2half2(__float2half(a), __float2half(b));
    return *reinterpret_cast<uint32_t*>(&h);
}
__device__ __forceinline__ void mma16816(float d[4], const uint32_t a[4], uint32_t b0, uint32_t b1){
    asm volatile("mma.sync.aligned.m16n8k16.row.col.f32.f16.f16.f32 "
        "{%0,%1,%2,%3},{%4,%5,%6,%7},{%8,%9},{%0,%1,%2,%3};"
        : "+f"(d[0]),"+f"(d[1]),"+f"(d[2]),"+f"(d[3])
        : "r"(a[0]),"r"(a[1]),"r"(a[2]),"r"(a[3]),"r"(b0),"r"(b1));
}
__device__ __forceinline__ float cellh(float gi, float gf, float gg, float go, float& c){
    float i_=sig_mufu(gi), f_=sig_mufu(gf), g_=tanh_mufu(gg), o_=sig_mufu(go);
    c = fmaf(f_, c, i_*g_);
    return o_ * tanh_mufu(c);
}
__device__ __forceinline__ float hhi_f(float w){ return __half2float(__float2half(w)); }

// B element (k, gate-row r). A k-layouts:
// A0: ones@0,1 | xhi@2-4 (Whi) | xhi@5-7 (Wlo) | xlo@8-10 (Whi) | pad@11 | h0hi@12-41 (Whi) | h0hi@42-71 (Wlo) | pad
// A1: ones@0,1 | h0hi@2-31 (Whi) | h0hi@32-61 (Wlo) | h1hi@62-91 (Whi) | h1hi@92-121 (Wlo) | pad
__device__ float b0v(int k, int r, const float* Wih0, const float* Whh0,
                     const float* bih0, const float* bhh0){
    if (k < 2)  { float b=bih0[r]+bhh0[r]; float h=hhi_f(b); return k==0? h : b-h; }
    if (k < 5)  { return hhi_f(Wih0[r*INP + (k-2)]); }
    if (k < 8)  { float w=Wih0[r*INP + (k-5)]; return w - hhi_f(w); }
    if (k < 11) { return hhi_f(Wih0[r*INP + (k-8)]); }
    if (k < 12) return 0.f;
    if (k < 42) { return hhi_f(Whh0[r*HH + (k-12)]); }
    if (k < 72) { float w=Whh0[r*HH + (k-42)]; return w - hhi_f(w); }
    return 0.f;
}
__device__ float b1v(int k, int r, const float* Wih1, const float* Whh1,
                     const float* bih1, const float* bhh1){
    if (k < 2)   { float b=bih1[r]+bhh1[r]; float h=hhi_f(b); return k==0? h : b-h; }
    if (k < 32)  { return hhi_f(Wih1[r*HH + (k-2)]); }
    if (k < 62)  { float w=Wih1[r*HH + (k-32)]; return w - hhi_f(w); }
    if (k < 92)  { return hhi_f(Whh1[r*HH + (k-62)]); }
    if (k < 122) { float w=Whh1[r*HH + (k-92)]; return w - hhi_f(w); }
    return 0.f;
}

__global__ void __launch_bounds__(NTHR, 1)
stacked_lstm_hmma(const float* __restrict__ x,
                  const float* __restrict__ Wih0, const float* __restrict__ Whh0,
                  const float* __restrict__ bih0, const float* __restrict__ bhh0,
                  const float* __restrict__ Wih1, const float* __restrict__ Whh1,
                  const float* __restrict__ bih1, const float* __restrict__ bhh1,
                  const float* __restrict__ Wfc1, const float* __restrict__ bfc1,
                  const float* __restrict__ Wfc2, const float* __restrict__ bfc2,
                  const float* __restrict__ Wfc3, const float* __restrict__ bfc3,
                  float* __restrict__ out, int B)
{
    extern __shared__ char sm[];
    const int tid  = threadIdx.x;
    const int wid  = tid >> 5;
    const int lane = tid & 31;
    const int grp  = lane >> 2;
    const int tig  = lane & 3;
    const int rt   = wid >> 2;      // row tile 0..3
    const int nq   = wid & 3;       // N quarter
    const int ntb  = nq * 4;
    const int NTn  = (nq == 3) ? 3 : 4;
    const int row0 = rt*16 + grp;
    const int rowE = row0 + ((tig & 1) << 3);
    const int xrow = tid >> 3, xc = tid & 7;
    const bool xact = (xc < 3);
    const unsigned FULL = 0xffffffffu;

    // ================= preamble =================
    for (int i = tid; i < (2*A0BUFB + 2*A1BUFB)/4; i += NTHR)
        ((uint32_t*)(sm + SM_A0))[i] = 0u;

    uint2* bfr = (uint2*)(sm + SM_BF);
    for (int idx = tid; idx < NTILET*32; idx += NTHR) {
        int ln = idx & 31, gt = idx >> 5;
        int layer = (gt >= NTILE0);
        int lt = layer ? gt - NTILE0 : gt;
        int kt = lt / 15, nt = lt % 15;
        int n  = nt*8 + (ln >> 2);
        int j  = n >> 2, g = n & 3;
        int r  = g*HH + j;
        int k0 = kt*16 + 2*(ln & 3);
        float v00, v01, v10, v11;
        if (!layer) {
            v00=b0v(k0,r,Wih0,Whh0,bih0,bhh0);   v01=b0v(k0+1,r,Wih0,Whh0,bih0,bhh0);
            v10=b0v(k0+8,r,Wih0,Whh0,bih0,bhh0); v11=b0v(k0+9,r,Wih0,Whh0,bih0,bhh0);
        } else {
            v00=b1v(k0,r,Wih1,Whh1,bih1,bhh1);   v01=b1v(k0+1,r,Wih1,Whh1,bih1,bhh1);
            v10=b1v(k0+8,r,Wih1,Whh1,bih1,bhh1); v11=b1v(k0+9,r,Wih1,Whh1,bih1,bhh1);
        }
        bfr[gt*32 + ln] = make_uint2(pkhf(v00, v01), pkhf(v10, v11));
    }
    float* fcs = (float*)(sm + SM_FC);
    for (int i = tid; i < 64*HH; i += NTHR) fcs[i] = Wfc1[i];
    for (int i = tid; i < 64; i += NTHR)    fcs[1920 + i] = bfc1[i];
    for (int i = tid; i < 32*64; i += NTHR) fcs[1984 + i] = Wfc2[i];
    for (int i = tid; i < 32; i += NTHR) { fcs[4032 + i] = bfc2[i]; fcs[4064 + i] = Wfc3[i]; }
    if (tid == 0) fcs[4096] = bfc3[0];
    __syncthreads();

    // ones (cols 0,1 fp16 = 1.0) in every row, both buffers, both A matrices
    if (tid < 2*ROWS) {
        int b = tid >> 6, row = tid & 63;
        *(uint32_t*)(sm + SM_A0 + b*A0BUFB + row*A0ROWB) = 0x3C003C00u;
        *(uint32_t*)(sm + SM_A1 + b*A1BUFB + row*A1ROWB) = 0x3C003C00u;
    }
    // x(0) into A0 buf0
    const float* xptr = x + ((size_t)blockIdx.x*ROWS + xrow)*TT*INP + xc;
    if (xact) {
        float xv = xptr[0];
        __half hi = __float2half(xv);
        __half lo = __float2half(xv - __half2float(hi));
        __half* an = (__half*)(sm + SM_A0 + xrow*A0ROWB);
        an[2+xc] = hi; an[5+xc] = hi; an[8+xc] = lo;
    }
    __syncthreads();

    // ================= merged-phase recurrence =================
    float cst0[4], cst1[4];
    #pragma unroll
    for (int i = 0; i < 4; i++) { cst0[i] = 0.f; cst1[i] = 0.f; }

    float* hfc = (float*)(sm + SM_BF);   // aliases B0 frags; written only at phase TT

    for (int p = 0; p <= TT; p++) {
        const int rb = p & 1, wbuf = rb ^ 1;

        // x load for next step (early issue)
        float xn = 0.f;
        const bool xload = (p + 1 < TT) && xact;
        if (xload) xn = xptr[(size_t)(p+1)*INP];

        // ---------- L0: gates0(p), active p < TT ----------
        if (p < TT) {
            float acc[4][4];
            #pragma unroll
            for (int n2 = 0; n2 < 4; n2++)
                { acc[n2][0]=0.f; acc[n2][1]=0.f; acc[n2][2]=0.f; acc[n2][3]=0.f; }
            const char* ab = sm + SM_A0 + rb*A0BUFB + row0*A0ROWB;
            #pragma unroll
            for (int kt = 0; kt < NK0; kt++) {
                uint32_t a[4];
                const char* q = ab + kt*32 + tig*4;
                a[0] = *(const uint32_t*)(q);
                a[1] = *(const uint32_t*)(q + 8*A0ROWB);
                a[2] = *(const uint32_t*)(q + 16);
                a[3] = *(const uint32_t*)(q + 8*A0ROWB + 16);
                #pragma unroll
                for (int n2 = 0; n2 < 4; n2++) {
                    if (n2 < NTn) {
                        uint2 bf = bfr[(kt*15 + ntb + n2)*32 + lane];
                        mma16816(acc[n2], a, bf.x, bf.y);
                    }
                }
            }
            // epilogue L0
            #pragma unroll
            for (int n2 = 0; n2 < 4; n2++) {
                if (n2 < NTn) {
                    float p0 = __shfl_xor_sync(FULL, acc[n2][0], 1);
                    float p1 = __shfl_xor_sync(FULL, acc[n2][1], 1);
                    float p2 = __shfl_xor_sync(FULL, acc[n2][2], 1);
                    float p3 = __shfl_xor_sync(FULL, acc[n2][3], 1);
                    float gi, gf, gg, go;
                    if ((tig & 1) == 0) { gi = acc[n2][0]; gf = acc[n2][1]; gg = p0; go = p1; }
                    else                { gi = p2;         gf = p3;         gg = acc[n2][2]; go = acc[n2][3]; }
                    float h = cellh(gi, gf, gg, go, cst0[n2]);
                    __half hv = __float2half(h);
                    int j = 2*(ntb + n2) + (tig >> 1);
                    __half* a0w = (__half*)(sm + SM_A0 + wbuf*A0BUFB + rowE*A0ROWB);
                    a0w[12+j] = hv; a0w[42+j] = hv;
                    __half* a1w = (__half*)(sm + SM_A1 + wbuf*A1BUFB + rowE*A1ROWB);
                    a1w[2+j] = hv; a1w[32+j] = hv;
                }
            }
            // x(p+1) into A0[wbuf]
            if (xload) {
                __half hi = __float2half(xn);
                __half lo = __float2half(xn - __half2float(hi));
                __half* an = (__half*)(sm + SM_A0 + wbuf*A0BUFB + xrow*A0ROWB);
                an[2+xc] = hi; an[5+xc] = hi; an[8+xc] = lo;
            }
        }

        // ---------- L1: gates1(p-1), active p >= 1 ----------
        if (p >= 1) {
            float acc[4][4];
            #pragma unroll
            for (int n2 = 0; n2 < 4; n2++)
                { acc[n2][0]=0.f; acc[n2][1]=0.f; acc[n2][2]=0.f; acc[n2][3]=0.f; }
            const char* ab = sm + SM_A1 + rb*A1BUFB + row0*A1ROWB;
            #pragma unroll
            for (int kt = 0; kt < NK1; kt++) {
                uint32_t a[4];
                const char* q = ab + kt*32 + tig*4;
                a[0] = *(const uint32_t*)(q);
                a[1] = *(const uint32_t*)(q + 8*A1ROWB);
                a[2] = *(const uint32_t*)(q + 16);
                a[3] = *(const uint32_t*)(q + 8*A1ROWB + 16);
                #pragma unroll
                for (int n2 = 0; n2 < 4; n2++) {
                    if (n2 < NTn) {
                        uint2 bf = bfr[(NTILE0 + kt*15 + ntb + n2)*32 + lane];
                        mma16816(acc[n2], a, bf.x, bf.y);
                    }
                }
            }
            // epilogue L1
            #pragma unroll
            for (int n2 = 0; n2 < 4; n2++) {
                if (n2 < NTn) {
                    float p0 = __shfl_xor_sync(FULL, acc[n2][0], 1);
                    float p1 = __shfl_xor_sync(FULL, acc[n2][1], 1);
                    float p2 = __shfl_xor_sync(FULL, acc[n2][2], 1);
                    float p3 = __shfl_xor_sync(FULL, acc[n2][3], 1);
                    float gi, gf, gg, go;
                    if ((tig & 1) == 0) { gi = acc[n2][0]; gf = acc[n2][1]; gg = p0; go = p1; }
                    else                { gi = p2;         gf = p3;         gg = acc[n2][2]; go = acc[n2][3]; }
                    float h = cellh(gi, gf, gg, go, cst1[n2]);
                    __half hv = __float2half(h);
                    int j = 2*(ntb + n2) + (tig >> 1);
                    __half* a1w = (__half*)(sm + SM_A1 + wbuf*A1BUFB + rowE*A1ROWB);
                    a1w[62+j] = hv; a1w[92+j] = hv;
                    if (p == TT) hfc[rowE*32 + j] = h;   // fp32 stash (B0 frags dead)
                }
            }
        }
        __syncthreads();
    }

    // ================= FC head (threads 0..63, fp32 h1) =================
    if (tid < ROWS) {
        float h1f[HH];
        #pragma unroll
        for (int u = 0; u < HH; u++) h1f[u] = hfc[tid*32 + u];

        float z2[32];
        #pragma unroll
        for (int o = 0; o < 32; o++) z2[o] = fcs[4032 + o];
        for (int k = 0; k < 64; k++) {
            float z = fcs[1920 + k];
            #pragma unroll
            for (int c = 0; c < HH; c++) z = fmaf(fcs[k*HH + c], h1f[c], z);
            z = fmaxf(z, 0.0f);
            #pragma unroll
            for (int o = 0; o < 32; o++) z2[o] = fmaf(fcs[1984 + o*64 + k], z, z2[o]);
        }
        float acc = fcs[4096];
        #pragma unroll
        for (int o = 0; o < 32; o++) acc = fmaf(fcs[4064 + o], fmaxf(z2[o], 0.0f), acc);
        out[(size_t)blockIdx.x*ROWS + tid] = __fdividef(1.0f, 1.0f + __expf(-acc));
    }
}

extern "C" void kernel_launch(void* const* d_in, const int* in_sizes, int n_in,
                              void* d_out, int out_size)
{
    const float* x    = (const float*)d_in[0];
    const float* Wih0 = (const float*)d_in[1];
    const float* Whh0 = (const float*)d_in[2];
    const float* bih0 = (const float*)d_in[3];
    const float* bhh0 = (const float*)d_in[4];
    const float* Wih1 = (const float*)d_in[5];
    const float* Whh1 = (const float*)d_in[6];
    const float* bih1 = (const float*)d_in[7];
    const float* bhh1 = (const float*)d_in[8];
    const float* Wfc1 = (const float*)d_in[9];
    const float* bfc1 = (const float*)d_in[10];
    const float* Wfc2 = (const float*)d_in[11];
    const float* bfc2 = (const float*)d_in[12];
    const float* Wfc3 = (const float*)d_in[13];
    const float* bfc3 = (const float*)d_in[14];
    float* out = (float*)d_out;

    int B = in_sizes[0] / (TT * INP);   // 8192
    int blocks = B / ROWS;              // 128

    cudaFuncSetAttribute(stacked_lstm_hmma,
                         cudaFuncAttributeMaxDynamicSharedMemorySize, SM_TOTAL);

    stacked_lstm_hmma<<<blocks, NTHR, SM_TOTAL>>>(x,
        Wih0, Whh0, bih0, bhh0,
        Wih1, Whh1, bih1, bhh1,
        Wfc1, bfc1, Wfc2, bfc2, Wfc3, bfc3,
        out, B);
}

// round 13
// speedup vs baseline: 4.3024x; 1.4471x over previous
#include <cuda_runtime.h>
#include <cuda_fp16.h>
#include <cstdint>

#define TT   256
#define HH   30
#define INP  3
#define ROWS 64
#define NTHR 512
#define NK0  3              // K0 = 48
#define NK1  4              // K1 = 64

#define A0STR 56            // fp16 per A0 row (28 words: grp*28 mod 32 distinct)
#define A1STR 72            // fp16 per A1 row (36 words: grp*4 mod 32 distinct)
#define A0ROWB (A0STR*2)    // 112
#define A1ROWB (A1STR*2)    // 144
#define A0BUFB (ROWS*A0ROWB)   // 7168
#define A1BUFB (ROWS*A1ROWB)   // 9216

#define SM_BF   0
#define NTILE0  (NK0*15)                 // 45 layer0 tiles
#define NTILET  (NTILE0 + NK1*15)        // 105 total
#define BF_SZ   (NTILET*256)             // 26880
#define SM_A0   BF_SZ
#define SM_A1   (SM_A0 + 2*A0BUFB)       // 41216
#define SM_FC   (SM_A1 + 2*A1BUFB)       // 59648
#define SM_TOTAL (SM_FC + 4097*4)        // 76036
// fp32 h1 stash for FC head aliases the B0 fragment region (dead at phase TT)

__device__ __forceinline__ float tanh_mufu(float x){ float r; asm("tanh.approx.f32 %0,%1;":"=f"(r):"f"(x)); return r; }
__device__ __forceinline__ float sig_mufu(float x){ return fmaf(0.5f, tanh_mufu(0.5f*x), 0.5f); }
__device__ __forceinline__ uint32_t pkhf(float a, float b){
    __half2 h = __halves2half2(__float2half(a), __float2half(b));
    return *reinterpret_cast<uint32_t*>(&h);
}
__device__ __forceinline__ void mma16816(float d[4], const uint32_t a[4], uint32_t b0, uint32_t b1){
    asm volatile("mma.sync.aligned.m16n8k16.row.col.f32.f16.f16.f32 "
        "{%0,%1,%2,%3},{%4,%5,%6,%7},{%8,%9},{%0,%1,%2,%3};"
        : "+f"(d[0]),"+f"(d[1]),"+f"(d[2]),"+f"(d[3])
        : "r"(a[0]),"r"(a[1]),"r"(a[2]),"r"(a[3]),"r"(b0),"r"(b1));
}
__device__ __forceinline__ float cellh(float gi, float gf, float gg, float go, float& c){
    float i_=sig_mufu(gi), f_=sig_mufu(gf), g_=tanh_mufu(gg), o_=sig_mufu(go);
    c = fmaf(f_, c, i_*g_);
    return o_ * tanh_mufu(c);
}
__device__ __forceinline__ float hhi_f(float w){ return __half2float(__float2half(w)); }

// A k-layouts (single-term fp16):
// A0: ones@0,1 | xhi@2-4 | h0@5-34 | pad to 48
// A1: ones@0,1 | h0@2-31 | h1@32-61 | pad to 64
__device__ float b0v(int k, int r, const float* Wih0, const float* Whh0,
                     const float* bih0, const float* bhh0){
    if (k < 2)  { float b=bih0[r]+bhh0[r]; float h=hhi_f(b); return k==0? h : b-h; }
    if (k < 5)  { return Wih0[r*INP + (k-2)]; }     // quantized by pkhf
    if (k < 35) { return Whh0[r*HH + (k-5)]; }
    return 0.f;
}
__device__ float b1v(int k, int r, const float* Wih1, const float* Whh1,
                     const float* bih1, const float* bhh1){
    if (k < 2)  { float b=bih1[r]+bhh1[r]; float h=hhi_f(b); return k==0? h : b-h; }
    if (k < 32) { return Wih1[r*HH + (k-2)]; }
    if (k < 62) { return Whh1[r*HH + (k-32)]; }
    return 0.f;
}

__global__ void __launch_bounds__(NTHR, 1)
stacked_lstm_hmma(const float* __restrict__ x,
                  const float* __restrict__ Wih0, const float* __restrict__ Whh0,
                  const float* __restrict__ bih0, const float* __restrict__ bhh0,
                  const float* __restrict__ Wih1, const float* __restrict__ Whh1,
                  const float* __restrict__ bih1, const float* __restrict__ bhh1,
                  const float* __restrict__ Wfc1, const float* __restrict__ bfc1,
                  const float* __restrict__ Wfc2, const float* __restrict__ bfc2,
                  const float* __restrict__ Wfc3, const float* __restrict__ bfc3,
                  float* __restrict__ out, int B)
{
    extern __shared__ char sm[];
    const int tid  = threadIdx.x;
    const int wid  = tid >> 5;
    const int lane = tid & 31;
    const int grp  = lane >> 2;
    const int tig  = lane & 3;
    const int rt   = wid >> 2;      // row tile 0..3
    const int nq   = wid & 3;       // N quarter
    const int ntb  = nq * 4;
    const int NTn  = (nq == 3) ? 3 : 4;
    const int row0 = rt*16 + grp;
    const int rowE = row0 + ((tig & 1) << 3);
    const int xrow = tid >> 3, xc = tid & 7;
    const bool xact = (xc < 3);
    const unsigned FULL = 0xffffffffu;

    // ================= preamble =================
    for (int i = tid; i < (2*A0BUFB + 2*A1BUFB)/4; i += NTHR)
        ((uint32_t*)(sm + SM_A0))[i] = 0u;

    uint2* bfr = (uint2*)(sm + SM_BF);
    for (int idx = tid; idx < NTILET*32; idx += NTHR) {
        int ln = idx & 31, gt = idx >> 5;
        int layer = (gt >= NTILE0);
        int lt = layer ? gt - NTILE0 : gt;
        int kt = lt / 15, nt = lt % 15;
        int n  = nt*8 + (ln >> 2);
        int j  = n >> 2, g = n & 3;
        int r  = g*HH + j;
        int k0 = kt*16 + 2*(ln & 3);
        float v00, v01, v10, v11;
        if (!layer) {
            v00=b0v(k0,r,Wih0,Whh0,bih0,bhh0);   v01=b0v(k0+1,r,Wih0,Whh0,bih0,bhh0);
            v10=b0v(k0+8,r,Wih0,Whh0,bih0,bhh0); v11=b0v(k0+9,r,Wih0,Whh0,bih0,bhh0);
        } else {
            v00=b1v(k0,r,Wih1,Whh1,bih1,bhh1);   v01=b1v(k0+1,r,Wih1,Whh1,bih1,bhh1);
            v10=b1v(k0+8,r,Wih1,Whh1,bih1,bhh1); v11=b1v(k0+9,r,Wih1,Whh1,bih1,bhh1);
        }
        bfr[gt*32 + ln] = make_uint2(pkhf(v00, v01), pkhf(v10, v11));
    }
    float* fcs = (float*)(sm + SM_FC);
    for (int i = tid; i < 64*HH; i += NTHR) fcs[i] = Wfc1[i];
    for (int i = tid; i < 64; i += NTHR)    fcs[1920 + i] = bfc1[i];
    for (int i = tid; i < 32*64; i += NTHR) fcs[1984 + i] = Wfc2[i];
    for (int i = tid; i < 32; i += NTHR) { fcs[4032 + i] = bfc2[i]; fcs[4064 + i] = Wfc3[i]; }
    if (tid == 0) fcs[4096] = bfc3[0];
    __syncthreads();

    // ones (cols 0,1 fp16 = 1.0) in every row, both buffers, both A matrices
    if (tid < 2*ROWS) {
        int b = tid >> 6, row = tid & 63;
        *(uint32_t*)(sm + SM_A0 + b*A0BUFB + row*A0ROWB) = 0x3C003C00u;
        *(uint32_t*)(sm + SM_A1 + b*A1BUFB + row*A1ROWB) = 0x3C003C00u;
    }
    // x(0) into A0 buf0
    const float* xptr = x + ((size_t)blockIdx.x*ROWS + xrow)*TT*INP + xc;
    if (xact) {
        __half* an = (__half*)(sm + SM_A0 + xrow*A0ROWB);
        an[2+xc] = __float2half(xptr[0]);
    }
    __syncthreads();

    // ================= merged-phase recurrence =================
    float cst0[4], cst1[4];
    #pragma unroll
    for (int i = 0; i < 4; i++) { cst0[i] = 0.f; cst1[i] = 0.f; }

    float* hfc = (float*)(sm + SM_BF);   // aliases B0 frags; written only at phase TT

    for (int p = 0; p <= TT; p++) {
        const int rb = p & 1, wbuf = rb ^ 1;

        // x load for next step (early issue)
        float xn = 0.f;
        const bool xload = (p + 1 < TT) && xact;
        if (xload) xn = xptr[(size_t)(p+1)*INP];

        // ---------- L0: gates0(p), active p < TT ----------
        if (p < TT) {
            float acc[4][4];
            #pragma unroll
            for (int n2 = 0; n2 < 4; n2++)
                { acc[n2][0]=0.f; acc[n2][1]=0.f; acc[n2][2]=0.f; acc[n2][3]=0.f; }
            const char* ab = sm + SM_A0 + rb*A0BUFB + row0*A0ROWB;
            #pragma unroll
            for (int kt = 0; kt < NK0; kt++) {
                uint32_t a[4];
                const char* q = ab + kt*32 + tig*4;
                a[0] = *(const uint32_t*)(q);
                a[1] = *(const uint32_t*)(q + 8*A0ROWB);
                a[2] = *(const uint32_t*)(q + 16);
                a[3] = *(const uint32_t*)(q + 8*A0ROWB + 16);
                #pragma unroll
                for (int n2 = 0; n2 < 4; n2++) {
                    if (n2 < NTn) {
                        uint2 bf = bfr[(kt*15 + ntb + n2)*32 + lane];
                        mma16816(acc[n2], a, bf.x, bf.y);
                    }
                }
            }
            // epilogue L0
            #pragma unroll
            for (int n2 = 0; n2 < 4; n2++) {
                if (n2 < NTn) {
                    float p0 = __shfl_xor_sync(FULL, acc[n2][0], 1);
                    float p1 = __shfl_xor_sync(FULL, acc[n2][1], 1);
                    float p2 = __shfl_xor_sync(FULL, acc[n2][2], 1);
                    float p3 = __shfl_xor_sync(FULL, acc[n2][3], 1);
                    float gi, gf, gg, go;
                    if ((tig & 1) == 0) { gi = acc[n2][0]; gf = acc[n2][1]; gg = p0; go = p1; }
                    else                { gi = p2;         gf = p3;         gg = acc[n2][2]; go = acc[n2][3]; }
                    float h = cellh(gi, gf, gg, go, cst0[n2]);
                    __half hv = __float2half(h);
                    int j = 2*(ntb + n2) + (tig >> 1);
                    ((__half*)(sm + SM_A0 + wbuf*A0BUFB + rowE*A0ROWB))[5+j] = hv;
                    ((__half*)(sm + SM_A1 + wbuf*A1BUFB + rowE*A1ROWB))[2+j] = hv;
                }
            }
            // x(p+1) into A0[wbuf]
            if (xload) {
                ((__half*)(sm + SM_A0 + wbuf*A0BUFB + xrow*A0ROWB))[2+xc] = __float2half(xn);
            }
        }

        // ---------- L1: gates1(p-1), active p >= 1 ----------
        if (p >= 1) {
            float acc[4][4];
            #pragma unroll
            for (int n2 = 0; n2 < 4; n2++)
                { acc[n2][0]=0.f; acc[n2][1]=0.f; acc[n2][2]=0.f; acc[n2][3]=0.f; }
            const char* ab = sm + SM_A1 + rb*A1BUFB + row0*A1ROWB;
            #pragma unroll
            for (int kt = 0; kt < NK1; kt++) {
                uint32_t a[4];
                const char* q = ab + kt*32 + tig*4;
                a[0] = *(const uint32_t*)(q);
                a[1] = *(const uint32_t*)(q + 8*A1ROWB);
                a[2] = *(const uint32_t*)(q + 16);
                a[3] = *(const uint32_t*)(q + 8*A1ROWB + 16);
                #pragma unroll
                for (int n2 = 0; n2 < 4; n2++) {
                    if (n2 < NTn) {
                        uint2 bf = bfr[(NTILE0 + kt*15 + ntb + n2)*32 + lane];
                        mma16816(acc[n2], a, bf.x, bf.y);
                    }
                }
            }
            // epilogue L1
            #pragma unroll
            for (int n2 = 0; n2 < 4; n2++) {
                if (n2 < NTn) {
                    float p0 = __shfl_xor_sync(FULL, acc[n2][0], 1);
                    float p1 = __shfl_xor_sync(FULL, acc[n2][1], 1);
                    float p2 = __shfl_xor_sync(FULL, acc[n2][2], 1);
                    float p3 = __shfl_xor_sync(FULL, acc[n2][3], 1);
                    float gi, gf, gg, go;
                    if ((tig & 1) == 0) { gi = acc[n2][0]; gf = acc[n2][1]; gg = p0; go = p1; }
                    else                { gi = p2;         gf = p3;         gg = acc[n2][2]; go = acc[n2][3]; }
                    float h = cellh(gi, gf, gg, go, cst1[n2]);
                    int j = 2*(ntb + n2) + (tig >> 1);
                    ((__half*)(sm + SM_A1 + wbuf*A1BUFB + rowE*A1ROWB))[32+j] = __float2half(h);
                    if (p == TT) hfc[rowE*32 + j] = h;   // fp32 stash (B0 frags dead)
                }
            }
        }
        __syncthreads();
    }

    // ================= FC head (threads 0..63, fp32 h1) =================
    if (tid < ROWS) {
        float h1f[HH];
        #pragma unroll
        for (int u = 0; u < HH; u++) h1f[u] = hfc[tid*32 + u];

        float z2[32];
        #pragma unroll
        for (int o = 0; o < 32; o++) z2[o] = fcs[4032 + o];
        for (int k = 0; k < 64; k++) {
            float z = fcs[1920 + k];
            #pragma unroll
            for (int c = 0; c < HH; c++) z = fmaf(fcs[k*HH + c], h1f[c], z);
            z = fmaxf(z, 0.0f);
            #pragma unroll
            for (int o = 0; o < 32; o++) z2[o] = fmaf(fcs[1984 + o*64 + k], z, z2[o]);
        }
        float acc = fcs[4096];
        #pragma unroll
        for (int o = 0; o < 32; o++) acc = fmaf(fcs[4064 + o], fmaxf(z2[o], 0.0f), acc);
        out[(size_t)blockIdx.x*ROWS + tid] = __fdividef(1.0f, 1.0f + __expf(-acc));
    }
}

extern "C" void kernel_launch(void* const* d_in, const int* in_sizes, int n_in,
                              void* d_out, int out_size)
{
    const float* x    = (const float*)d_in[0];
    const float* Wih0 = (const float*)d_in[1];
    const float* Whh0 = (const float*)d_in[2];
    const float* bih0 = (const float*)d_in[3];
    const float* bhh0 = (const float*)d_in[4];
    const float* Wih1 = (const float*)d_in[5];
    const float* Whh1 = (const float*)d_in[6];
    const float* bih1 = (const float*)d_in[7];
    const float* bhh1 = (const float*)d_in[8];
    const float* Wfc1 = (const float*)d_in[9];
    const float* bfc1 = (const float*)d_in[10];
    const float* Wfc2 = (const float*)d_in[11];
    const float* bfc2 = (const float*)d_in[12];
    const float* Wfc3 = (const float*)d_in[13];
    const float* bfc3 = (const float*)d_in[14];
    float* out = (float*)d_out;

    int B = in_sizes[0] / (TT * INP);   // 8192
    int blocks = B / ROWS;              // 128

    cudaFuncSetAttribute(stacked_lstm_hmma,
                         cudaFuncAttributeMaxDynamicSharedMemorySize, SM_TOTAL);

    stacked_lstm_hmma<<<blocks, NTHR, SM_TOTAL>>>(x,
        Wih0, Whh0, bih0, bhh0,
        Wih1, Whh1, bih1, bhh1,
        Wfc1, bfc1, Wfc2, bfc2, Wfc3, bfc3,
        out, B);
}

// round 14
// speedup vs baseline: 5.1655x; 1.2006x over previous
#include <cuda_runtime.h>
#include <cuda_fp16.h>
#include <cstdint>

#define TT   256
#define HH   30
#define INP  3
#define ROWS 64
#define NTHR 512
#define NK0  3              // K0 = 48
#define NK1  4              // K1 = 64

#define A0STR 56            // fp16 per A0 row
#define A1STR 72            // fp16 per A1 row
#define A0ROWB (A0STR*2)    // 112
#define A1ROWB (A1STR*2)    // 144
#define A0BUFB (ROWS*A0ROWB)   // 7168
#define A1BUFB (ROWS*A1ROWB)   // 9216

#define SM_BF   0
#define NTILE0  (NK0*15)                 // 45
#define NTILET  (NTILE0 + NK1*15)        // 105
#define BF_SZ   (NTILET*256)             // 26880
#define SM_A0   BF_SZ
#define SM_A1   (SM_A0 + 2*A0BUFB)       // 41216
#define SM_FC   (SM_A1 + 2*A1BUFB)       // 59648
#define SM_HFC  (SM_FC + 4097*4)         // 76036
#define SM_TOTAL (SM_HFC + ROWS*32*4)    // 84228

__device__ __forceinline__ float tanh_mufu(float x){ float r; asm("tanh.approx.f32 %0,%1;":"=f"(r):"f"(x)); return r; }
__device__ __forceinline__ float sig_mufu(float x){ return fmaf(0.5f, tanh_mufu(0.5f*x), 0.5f); }
__device__ __forceinline__ uint32_t pkhf(float a, float b){
    __half2 h = __halves2half2(__float2half(a), __float2half(b));
    return *reinterpret_cast<uint32_t*>(&h);
}
__device__ __forceinline__ void mma16816(float d[4], const uint32_t a[4], uint32_t b0, uint32_t b1){
    asm volatile("mma.sync.aligned.m16n8k16.row.col.f32.f16.f16.f32 "
        "{%0,%1,%2,%3},{%4,%5,%6,%7},{%8,%9},{%0,%1,%2,%3};"
        : "+f"(d[0]),"+f"(d[1]),"+f"(d[2]),"+f"(d[3])
        : "r"(a[0]),"r"(a[1]),"r"(a[2]),"r"(a[3]),"r"(b0),"r"(b1));
}
__device__ __forceinline__ float cellh(float gi, float gf, float gg, float go, float& c){
    float i_=sig_mufu(gi), f_=sig_mufu(gf), g_=tanh_mufu(gg), o_=sig_mufu(go);
    c = fmaf(f_, c, i_*g_);
    return o_ * tanh_mufu(c);
}
__device__ __forceinline__ float hhi_f(float w){ return __half2float(__float2half(w)); }

// A k-layouts (single-term fp16):
// A0: ones@0,1 | x@2-4 | h0@5-34 | pad to 48
// A1: ones@0,1 | h0@2-31 | h1@32-61 | pad to 64
__device__ float b0v(int k, int r, const float* Wih0, const float* Whh0,
                     const float* bih0, const float* bhh0){
    if (k < 2)  { float b=bih0[r]+bhh0[r]; float h=hhi_f(b); return k==0? h : b-h; }
    if (k < 5)  { return Wih0[r*INP + (k-2)]; }
    if (k < 35) { return Whh0[r*HH + (k-5)]; }
    return 0.f;
}
__device__ float b1v(int k, int r, const float* Wih1, const float* Whh1,
                     const float* bih1, const float* bhh1){
    if (k < 2)  { float b=bih1[r]+bhh1[r]; float h=hhi_f(b); return k==0? h : b-h; }
    if (k < 32) { return Wih1[r*HH + (k-2)]; }
    if (k < 62) { return Whh1[r*HH + (k-32)]; }
    return 0.f;
}

__global__ void __launch_bounds__(NTHR, 1)
stacked_lstm_hmma(const float* __restrict__ x,
                  const float* __restrict__ Wih0, const float* __restrict__ Whh0,
                  const float* __restrict__ bih0, const float* __restrict__ bhh0,
                  const float* __restrict__ Wih1, const float* __restrict__ Whh1,
                  const float* __restrict__ bih1, const float* __restrict__ bhh1,
                  const float* __restrict__ Wfc1, const float* __restrict__ bfc1,
                  const float* __restrict__ Wfc2, const float* __restrict__ bfc2,
                  const float* __restrict__ Wfc3, const float* __restrict__ bfc3,
                  float* __restrict__ out, int B)
{
    extern __shared__ char sm[];
    const int tid  = threadIdx.x;
    const int wid  = tid >> 5;
    const int lane = tid & 31;
    const int grp  = lane >> 2;
    const int tig  = lane & 3;
    const int rt   = wid >> 2;      // team / row tile 0..3
    const int nq   = wid & 3;
    const int ntb  = nq * 4;
    const int NTn  = (nq == 3) ? 3 : 4;
    const int row0 = rt*16 + grp;
    const int rowE = row0 + ((tig & 1) << 3);
    const int tidt = tid & 127;                 // tid within team
    const int xrow = rt*16 + (tidt >> 3);       // team loads its own 16 rows
    const int xc   = tidt & 7;
    const bool xact = (xc < 3);
    const unsigned FULL = 0xffffffffu;

    // ================= preamble (full block) =================
    for (int i = tid; i < (2*A0BUFB + 2*A1BUFB)/4; i += NTHR)
        ((uint32_t*)(sm + SM_A0))[i] = 0u;

    uint2* bfr = (uint2*)(sm + SM_BF);
    for (int idx = tid; idx < NTILET*32; idx += NTHR) {
        int ln = idx & 31, gt = idx >> 5;
        int layer = (gt >= NTILE0);
        int lt = layer ? gt - NTILE0 : gt;
        int kt = lt / 15, nt = lt % 15;
        int n  = nt*8 + (ln >> 2);
        int j  = n >> 2, g = n & 3;
        int r  = g*HH + j;
        int k0 = kt*16 + 2*(ln & 3);
        float v00, v01, v10, v11;
        if (!layer) {
            v00=b0v(k0,r,Wih0,Whh0,bih0,bhh0);   v01=b0v(k0+1,r,Wih0,Whh0,bih0,bhh0);
            v10=b0v(k0+8,r,Wih0,Whh0,bih0,bhh0); v11=b0v(k0+9,r,Wih0,Whh0,bih0,bhh0);
        } else {
            v00=b1v(k0,r,Wih1,Whh1,bih1,bhh1);   v01=b1v(k0+1,r,Wih1,Whh1,bih1,bhh1);
            v10=b1v(k0+8,r,Wih1,Whh1,bih1,bhh1); v11=b1v(k0+9,r,Wih1,Whh1,bih1,bhh1);
        }
        bfr[gt*32 + ln] = make_uint2(pkhf(v00, v01), pkhf(v10, v11));
    }
    float* fcs = (float*)(sm + SM_FC);
    for (int i = tid; i < 64*HH; i += NTHR) fcs[i] = Wfc1[i];
    for (int i = tid; i < 64; i += NTHR)    fcs[1920 + i] = bfc1[i];
    for (int i = tid; i < 32*64; i += NTHR) fcs[1984 + i] = Wfc2[i];
    for (int i = tid; i < 32; i += NTHR) { fcs[4032 + i] = bfc2[i]; fcs[4064 + i] = Wfc3[i]; }
    if (tid == 0) fcs[4096] = bfc3[0];
    __syncthreads();

    if (tid < 2*ROWS) {
        int b = tid >> 6, row = tid & 63;
        *(uint32_t*)(sm + SM_A0 + b*A0BUFB + row*A0ROWB) = 0x3C003C00u;
        *(uint32_t*)(sm + SM_A1 + b*A1BUFB + row*A1ROWB) = 0x3C003C00u;
    }
    const float* xptr = x + ((size_t)blockIdx.x*ROWS + xrow)*TT*INP + xc;
    if (xact) {
        ((__half*)(sm + SM_A0 + xrow*A0ROWB))[2+xc] = __float2half(xptr[0]);
    }
    __syncthreads();

    // ================= per-team merged-phase recurrence =================
    float cst0[4], cst1[4];
    #pragma unroll
    for (int i = 0; i < 4; i++) { cst0[i] = 0.f; cst1[i] = 0.f; }

    float* hfc = (float*)(sm + SM_HFC);
    const int barid = rt + 1;

    for (int p = 0; p <= TT; p++) {
        const int rb = p & 1, wbuf = rb ^ 1;

        float xn = 0.f;
        const bool xload = (p + 1 < TT) && xact;
        if (xload) xn = xptr[(size_t)(p+1)*INP];

        // ---------- L0: gates0(p), p < TT ----------
        if (p < TT) {
            float acc[4][4];
            #pragma unroll
            for (int n2 = 0; n2 < 4; n2++)
                { acc[n2][0]=0.f; acc[n2][1]=0.f; acc[n2][2]=0.f; acc[n2][3]=0.f; }
            const char* ab = sm + SM_A0 + rb*A0BUFB + row0*A0ROWB;
            #pragma unroll
            for (int kt = 0; kt < NK0; kt++) {
                uint32_t a[4];
                const char* q = ab + kt*32 + tig*4;
                a[0] = *(const uint32_t*)(q);
                a[1] = *(const uint32_t*)(q + 8*A0ROWB);
                a[2] = *(const uint32_t*)(q + 16);
                a[3] = *(const uint32_t*)(q + 8*A0ROWB + 16);
                #pragma unroll
                for (int n2 = 0; n2 < 4; n2++) {
                    if (n2 < NTn) {
                        uint2 bf = bfr[(kt*15 + ntb + n2)*32 + lane];
                        mma16816(acc[n2], a, bf.x, bf.y);
                    }
                }
            }
            #pragma unroll
            for (int n2 = 0; n2 < 4; n2++) {
                if (n2 < NTn) {
                    float p0 = __shfl_xor_sync(FULL, acc[n2][0], 1);
                    float p1 = __shfl_xor_sync(FULL, acc[n2][1], 1);
                    float p2 = __shfl_xor_sync(FULL, acc[n2][2], 1);
                    float p3 = __shfl_xor_sync(FULL, acc[n2][3], 1);
                    float gi, gf, gg, go;
                    if ((tig & 1) == 0) { gi = acc[n2][0]; gf = acc[n2][1]; gg = p0; go = p1; }
                    else                { gi = p2;         gf = p3;         gg = acc[n2][2]; go = acc[n2][3]; }
                    float h = cellh(gi, gf, gg, go, cst0[n2]);
                    __half hv = __float2half(h);
                    int j = 2*(ntb + n2) + (tig >> 1);
                    ((__half*)(sm + SM_A0 + wbuf*A0BUFB + rowE*A0ROWB))[5+j] = hv;
                    ((__half*)(sm + SM_A1 + wbuf*A1BUFB + rowE*A1ROWB))[2+j] = hv;
                }
            }
            if (xload) {
                ((__half*)(sm + SM_A0 + wbuf*A0BUFB + xrow*A0ROWB))[2+xc] = __float2half(xn);
            }
        }

        // ---------- L1: gates1(p-1), p >= 1 ----------
        if (p >= 1) {
            float acc[4][4];
            #pragma unroll
            for (int n2 = 0; n2 < 4; n2++)
                { acc[n2][0]=0.f; acc[n2][1]=0.f; acc[n2][2]=0.f; acc[n2][3]=0.f; }
            const char* ab = sm + SM_A1 + rb*A1BUFB + row0*A1ROWB;
            #pragma unroll
            for (int kt = 0; kt < NK1; kt++) {
                uint32_t a[4];
                const char* q = ab + kt*32 + tig*4;
                a[0] = *(const uint32_t*)(q);
                a[1] = *(const uint32_t*)(q + 8*A1ROWB);
                a[2] = *(const uint32_t*)(q + 16);
                a[3] = *(const uint32_t*)(q + 8*A1ROWB + 16);
                #pragma unroll
                for (int n2 = 0; n2 < 4; n2++) {
                    if (n2 < NTn) {
                        uint2 bf = bfr[(NTILE0 + kt*15 + ntb + n2)*32 + lane];
                        mma16816(acc[n2], a, bf.x, bf.y);
                    }
                }
            }
            #pragma unroll
            for (int n2 = 0; n2 < 4; n2++) {
                if (n2 < NTn) {
                    float p0 = __shfl_xor_sync(FULL, acc[n2][0], 1);
                    float p1 = __shfl_xor_sync(FULL, acc[n2][1], 1);
                    float p2 = __shfl_xor_sync(FULL, acc[n2][2], 1);
                    float p3 = __shfl_xor_sync(FULL, acc[n2][3], 1);
                    float gi, gf, gg, go;
                    if ((tig & 1) == 0) { gi = acc[n2][0]; gf = acc[n2][1]; gg = p0; go = p1; }
                    else                { gi = p2;         gf = p3;         gg = acc[n2][2]; go = acc[n2][3]; }
                    float h = cellh(gi, gf, gg, go, cst1[n2]);
                    int j = 2*(ntb + n2) + (tig >> 1);
                    ((__half*)(sm + SM_A1 + wbuf*A1BUFB + rowE*A1ROWB))[32+j] = __float2half(h);
                    if (p == TT) hfc[rowE*32 + j] = h;
                }
            }
        }
        // team-local barrier: only this row-tile's 128 threads synchronize
        asm volatile("bar.sync %0, %1;" :: "r"(barid), "r"(128) : "memory");
    }

    __syncthreads();   // hfc complete across all teams

    // ================= FC head (threads 0..63, fp32 h1) =================
    if (tid < ROWS) {
        float h1f[HH];
        #pragma unroll
        for (int u = 0; u < HH; u++) h1f[u] = hfc[tid*32 + u];

        float z2[32];
        #pragma unroll
        for (int o = 0; o < 32; o++) z2[o] = fcs[4032 + o];
        for (int k = 0; k < 64; k++) {
            float z = fcs[1920 + k];
            #pragma unroll
            for (int c = 0; c < HH; c++) z = fmaf(fcs[k*HH + c], h1f[c], z);
            z = fmaxf(z, 0.0f);
            #pragma unroll
            for (int o = 0; o < 32; o++) z2[o] = fmaf(fcs[1984 + o*64 + k], z, z2[o]);
        }
        float acc = fcs[4096];
        #pragma unroll
        for (int o = 0; o < 32; o++) acc = fmaf(fcs[4064 + o], fmaxf(z2[o], 0.0f), acc);
        out[(size_t)blockIdx.x*ROWS + tid] = __fdividef(1.0f, 1.0f + __expf(-acc));
    }
}

extern "C" void kernel_launch(void* const* d_in, const int* in_sizes, int n_in,
                              void* d_out, int out_size)
{
    const float* x    = (const float*)d_in[0];
    const float* Wih0 = (const float*)d_in[1];
    const float* Whh0 = (const float*)d_in[2];
    const float* bih0 = (const float*)d_in[3];
    const float* bhh0 = (const float*)d_in[4];
    const float* Wih1 = (const float*)d_in[5];
    const float* Whh1 = (const float*)d_in[6];
    const float* bih1 = (const float*)d_in[7];
    const float* bhh1 = (const float*)d_in[8];
    const float* Wfc1 = (const float*)d_in[9];
    const float* bfc1 = (const float*)d_in[10];
    const float* Wfc2 = (const float*)d_in[11];
    const float* bfc2 = (const float*)d_in[12];
    const float* Wfc3 = (const float*)d_in[13];
    const float* bfc3 = (const float*)d_in[14];
    float* out = (float*)d_out;

    int B = in_sizes[0] / (TT * INP);   // 8192
    int blocks = B / ROWS;              // 128

    cudaFuncSetAttribute(stacked_lstm_hmma,
                         cudaFuncAttributeMaxDynamicSharedMemorySize, SM_TOTAL);

    stacked_lstm_hmma<<<blocks, NTHR, SM_TOTAL>>>(x,
        Wih0, Whh0, bih0, bhh0,
        Wih1, Whh1, bih1, bhh1,
        Wfc1, bfc1, Wfc2, bfc2, Wfc3, bfc3,
        out, B);
}